// round 6
// baseline (speedup 1.0000x reference)
#include <cuda_runtime.h>
#include <cuda_bf16.h>

#define DINLINE __device__ __forceinline__
typedef unsigned int u32;
typedef unsigned short u16;

constexpr int B_ = 8, T_ = 64, N_ = 512, H_ = 128, E_ = 8192;
constexpr int S_ = B_ * N_;       // 4096 sequences
constexpr int G1_ = 128, G2_ = 64;
constexpr int G4H = 4 * H_;       // 512 gate rows

// ---------------- device scratch (static globals; no allocation) -------------
__device__ float g_h [(size_t)T_ * S_ * H_];     // [t*S+s][j]   128 MiB
__device__ float g_xp[(size_t)T_ * S_ * G4H];    // [t*S+s][4j+g] 512 MiB
__device__ __nv_bfloat16 g_whh_hi[3][G4H * H_];  // permuted rows (4j+g)
__device__ __nv_bfloat16 g_whh_lo[3][G4H * H_];
__device__ __nv_bfloat16 g_wih_hi[2][G4H * H_];
__device__ __nv_bfloat16 g_wih_lo[2][G4H * H_];
__device__ float g_br[3][G4H];                   // b_ih+b_hh, permuted
__device__ float g_w0r[G4H];                     // w_ih0 permuted
__device__ float g_xl1[S_ * G1_];
__device__ float g_h1[S_ * G1_];
__device__ float g_xl2[S_ * G2_];
__device__ float g_h2[S_ * G2_];
__device__ float g_deg[N_];
__device__ float g_dis[N_];
__device__ int   g_is64;

// ---------------- helpers ------------------------------------------------------
DINLINE float sigf(float x)  { return __fdividef(1.0f, 1.0f + __expf(-x)); }
DINLINE float tanh_(float x) { return __fdividef(2.0f, 1.0f + __expf(-2.0f * x)) - 1.0f; }

DINLINE u16 bfb(float f) { __nv_bfloat16 h = __float2bfloat16(f); return *(u16*)&h; }
DINLINE float bup(u16 b) { __nv_bfloat16 h = *(__nv_bfloat16*)&b; return __bfloat162float(h); }

DINLINE void mma16816(float* D, const u32* A, u32 b0, u32 b1) {
    asm("mma.sync.aligned.m16n8k16.row.col.f32.bf16.bf16.f32 "
        "{%0,%1,%2,%3},{%4,%5,%6,%7},{%8,%9},{%0,%1,%2,%3};"
        : "+f"(D[0]), "+f"(D[1]), "+f"(D[2]), "+f"(D[3])
        : "r"(A[0]), "r"(A[1]), "r"(A[2]), "r"(A[3]), "r"(b0), "r"(b1));
}

// ---------------- edge dtype detection + degree init ---------------------------
__global__ void k_detect(const int* __restrict__ ei32) {
    __shared__ int nz;
    int tid = threadIdx.x;
    if (tid == 0) nz = 0;
    if (tid < N_) g_deg[tid] = 1.0f;
    __syncthreads();
    int acc = 0;
    for (int i = 1 + 2 * tid; i < 2 * E_; i += 2 * blockDim.x) acc |= ei32[i];
    if (acc) atomicOr(&nz, 1);
    __syncthreads();
    if (tid == 0) g_is64 = (nz == 0) ? 1 : 0;
}

DINLINE int edge_at(const void* p, int is64, int idx) {
    return is64 ? (int)((const long long*)p)[idx] : ((const int*)p)[idx];
}

__global__ void k_deg(const void* __restrict__ ei) {
    int e = blockIdx.x * blockDim.x + threadIdx.x;
    if (e < E_) atomicAdd(&g_deg[edge_at(ei, g_is64, E_ + e)], 1.0f);
}

__global__ void k_dis() {
    int n = blockIdx.x * blockDim.x + threadIdx.x;
    if (n < N_) g_dis[n] = rsqrtf(g_deg[n]);
}

// ---------------- weight prep: permute rows (4j+g) + bf16 hi/lo split ----------
__global__ void k_prep_w(const float* __restrict__ w,
                         __nv_bfloat16* __restrict__ hi,
                         __nv_bfloat16* __restrict__ lo) {
    int i = blockIdx.x * blockDim.x + threadIdx.x;   // 65536
    int colp = i >> 7, k = i & 127;
    int j = colp >> 2, g = colp & 3;
    float v = w[(g * H_ + j) * H_ + k];
    __nv_bfloat16 h = __float2bfloat16(v);
    hi[i] = h;
    lo[i] = __float2bfloat16(v - __bfloat162float(h));
}

__global__ void k_prep_b(const float* __restrict__ bi, const float* __restrict__ bh,
                         float* __restrict__ outb) {
    int colp = blockIdx.x * blockDim.x + threadIdx.x;   // 512
    if (colp < G4H) {
        int j = colp >> 2, g = colp & 3;
        outb[colp] = bi[g * H_ + j] + bh[g * H_ + j];
    }
}

__global__ void k_prep_w0(const float* __restrict__ w, float* __restrict__ outw) {
    int colp = blockIdx.x * blockDim.x + threadIdx.x;
    if (colp < G4H) {
        int j = colp >> 2, g = colp & 3;
        outw[colp] = w[g * H_ + j];
    }
}

// ---------------- tensor-core LSTM recurrence -----------------------------------
// Block: 16 seqs, 256 threads (8 warps). Warp w owns gate-cols [64w, 64w+64).
// D[seq(16) x col'(8)] per mma n-tile. 3-term bf16 split (AhBh + AhBl + AlBh).
template <int MODE, int WRITE_ALL>
__global__ void __launch_bounds__(256, 2) rec_mma(
    const float* __restrict__ x,                 // MODE 0
    const __nv_bfloat16* __restrict__ whh_hi,
    const __nv_bfloat16* __restrict__ whh_lo,
    const float* __restrict__ w0r,               // MODE 0
    const float* __restrict__ br0)               // MODE 0
{
    __shared__ __align__(16) __nv_bfloat16 shh[2][16][136];
    __shared__ __align__(16) __nv_bfloat16 shl[2][16][136];
    __shared__ float sx[64][16];

    const int tid = threadIdx.x, wid = tid >> 5, lane = tid & 31;
    const int grp = lane >> 2, tid4 = lane & 3;
    const int s0 = blockIdx.x * 16;
    const bool evn = (tid4 & 1) == 0;
    const int myrow = evn ? grp : grp + 8;

    // zero h buffers (step 0 state), stage x (MODE 0)
    for (int i = tid; i < 16 * 136; i += 256) {
        int r = i / 136, c = i - r * 136;
        shh[0][r][c] = __float2bfloat16(0.0f);
        shl[0][r][c] = __float2bfloat16(0.0f);
    }
    if (MODE == 0) {
        for (int i = tid; i < 16 * 64; i += 256) {
            int t = i >> 4, m = i & 15;
            int s = s0 + m;
            sx[t][m] = x[(s >> 9) * (T_ * N_) + t * N_ + (s & (N_ - 1))];
        }
    }
    __syncthreads();

    float c_st[8];
#pragma unroll
    for (int q = 0; q < 8; q++) c_st[q] = 0.0f;

    for (int t = 0; t < T_; t++) {
        const int rb = t & 1, wb = rb ^ 1;
        const u32* ph = (const u32*)&shh[rb][0][0];
        const u32* pl = (const u32*)&shl[rb][0][0];

        u32 ahi[8][4];
#pragma unroll
        for (int ks = 0; ks < 8; ks++) {
            int w = ks * 8 + tid4;
            ahi[ks][0] = ph[grp * 68 + w];
            ahi[ks][1] = ph[(grp + 8) * 68 + w];
            ahi[ks][2] = ph[grp * 68 + w + 4];
            ahi[ks][3] = ph[(grp + 8) * 68 + w + 4];
        }

#pragma unroll 1
        for (int ntp = 0; ntp < 4; ntp++) {
            const int n0 = wid * 64 + ntp * 16;
            const __nv_bfloat16* w0p = whh_hi + (n0 + grp) * H_;
            const __nv_bfloat16* w1p = whh_hi + (n0 + 8 + grp) * H_;
            u32 b0h[8][2], b1h[8][2];
#pragma unroll
            for (int ks = 0; ks < 8; ks++) {
                b0h[ks][0] = *(const u32*)(w0p + ks * 16 + tid4 * 2);
                b0h[ks][1] = *(const u32*)(w0p + ks * 16 + tid4 * 2 + 8);
                b1h[ks][0] = *(const u32*)(w1p + ks * 16 + tid4 * 2);
                b1h[ks][1] = *(const u32*)(w1p + ks * 16 + tid4 * 2 + 8);
            }
            float D0[4] = {0, 0, 0, 0}, D1[4] = {0, 0, 0, 0};
#pragma unroll
            for (int ks = 0; ks < 8; ks++) {
                mma16816(D0, ahi[ks], b0h[ks][0], b0h[ks][1]);
                mma16816(D1, ahi[ks], b1h[ks][0], b1h[ks][1]);
            }
            const __nv_bfloat16* l0p = whh_lo + (n0 + grp) * H_;
            const __nv_bfloat16* l1p = whh_lo + (n0 + 8 + grp) * H_;
#pragma unroll
            for (int ks = 0; ks < 8; ks++) {
                u32 x0 = *(const u32*)(l0p + ks * 16 + tid4 * 2);
                u32 x1 = *(const u32*)(l0p + ks * 16 + tid4 * 2 + 8);
                mma16816(D0, ahi[ks], x0, x1);
                u32 y0 = *(const u32*)(l1p + ks * 16 + tid4 * 2);
                u32 y1 = *(const u32*)(l1p + ks * 16 + tid4 * 2 + 8);
                mma16816(D1, ahi[ks], y0, y1);
            }
#pragma unroll
            for (int ks = 0; ks < 8; ks++) {
                int w = ks * 8 + tid4;
                u32 al[4];
                al[0] = pl[grp * 68 + w];
                al[1] = pl[(grp + 8) * 68 + w];
                al[2] = pl[grp * 68 + w + 4];
                al[3] = pl[(grp + 8) * 68 + w + 4];
                mma16816(D0, al, b0h[ks][0], b0h[ks][1]);
                mma16816(D1, al, b1h[ks][0], b1h[ks][1]);
            }

            // add input contribution (xp or w0*x+b)
            if (MODE == 0) {
                float xA = sx[t][grp], xB = sx[t][grp + 8];
                float2 w00 = *(const float2*)&w0r[n0 + tid4 * 2];
                float2 bb0 = *(const float2*)&br0[n0 + tid4 * 2];
                float2 w01 = *(const float2*)&w0r[n0 + 8 + tid4 * 2];
                float2 bb1 = *(const float2*)&br0[n0 + 8 + tid4 * 2];
                D0[0] += xA * w00.x + bb0.x; D0[1] += xA * w00.y + bb0.y;
                D0[2] += xB * w00.x + bb0.x; D0[3] += xB * w00.y + bb0.y;
                D1[0] += xA * w01.x + bb1.x; D1[1] += xA * w01.y + bb1.y;
                D1[2] += xB * w01.x + bb1.x; D1[3] += xB * w01.y + bb1.y;
            } else {
                const float* xpb = g_xp + ((size_t)t * S_ + s0) * G4H;
                float2 pA0 = *(const float2*)&xpb[grp * G4H + n0 + tid4 * 2];
                float2 pB0 = *(const float2*)&xpb[(grp + 8) * G4H + n0 + tid4 * 2];
                float2 pA1 = *(const float2*)&xpb[grp * G4H + n0 + 8 + tid4 * 2];
                float2 pB1 = *(const float2*)&xpb[(grp + 8) * G4H + n0 + 8 + tid4 * 2];
                D0[0] += pA0.x; D0[1] += pA0.y; D0[2] += pB0.x; D0[3] += pB0.y;
                D1[0] += pA1.x; D1[1] += pA1.y; D1[2] += pB1.x; D1[3] += pB1.y;
            }

            // gate math (lane-pair shuffle to gather i,f,g,o)
#pragma unroll
            for (int hf = 0; hf < 2; hf++) {
                float* D = hf ? D1 : D0;
                float sv0 = evn ? D[2] : D[0];
                float rr0 = __shfl_xor_sync(0xffffffffu, sv0, 1);
                float sv1 = evn ? D[3] : D[1];
                float rr1 = __shfl_xor_sync(0xffffffffu, sv1, 1);
                float pi = evn ? D[0] : rr0;
                float pf = evn ? D[1] : rr1;
                float pg = evn ? rr0 : D[2];
                float po = evn ? rr1 : D[3];
                int nt = ntp * 2 + hf;
                float cn = sigf(pf) * c_st[nt] + sigf(pi) * tanh_(pg);
                c_st[nt] = cn;
                float hv = sigf(po) * tanh_(cn);
                int j = wid * 16 + ntp * 4 + hf * 2 + (tid4 >> 1);
                __nv_bfloat16 hh = __float2bfloat16(hv);
                shh[wb][myrow][j] = hh;
                shl[wb][myrow][j] = __float2bfloat16(hv - __bfloat162float(hh));
                if (WRITE_ALL || t == T_ - 1)
                    g_h[((size_t)t * S_ + s0 + myrow) * H_ + j] = hv;
            }
        }
        __syncthreads();
    }
}

// ---------------- tensor-core input projection -----------------------------------
// g_xp[row][col'] = h_prev[row] . W_ih[col'] + bias.  Block: 128 rows, 8 warps.
__global__ void __launch_bounds__(256, 2) proj_mma(
    const __nv_bfloat16* __restrict__ wih_hi,
    const __nv_bfloat16* __restrict__ wih_lo,
    const float* __restrict__ br)
{
    extern __shared__ __align__(16) u32 asm_[];   // [128][68] hi | [128][68] lo
    u32* AH = asm_;
    u32* AL = asm_ + 128 * 68;

    const int tid = threadIdx.x, wid = tid >> 5, lane = tid & 31;
    const int grp = lane >> 2, tid4 = lane & 3;
    const size_t r0 = (size_t)blockIdx.x * 128;

    // stage + split A (h rows)
    const float4* src = (const float4*)(g_h + r0 * H_);
    for (int i = tid; i < 128 * 32; i += 256) {
        int row = i >> 5, c4 = i & 31;
        float4 v = src[i];
        u16 hx = bfb(v.x), hy = bfb(v.y), hz = bfb(v.z), hw = bfb(v.w);
        AH[row * 68 + c4 * 2]     = ((u32)hy << 16) | hx;
        AH[row * 68 + c4 * 2 + 1] = ((u32)hw << 16) | hz;
        u16 lx = bfb(v.x - bup(hx)), ly = bfb(v.y - bup(hy));
        u16 lz = bfb(v.z - bup(hz)), lw = bfb(v.w - bup(hw));
        AL[row * 68 + c4 * 2]     = ((u32)ly << 16) | lx;
        AL[row * 68 + c4 * 2 + 1] = ((u32)lw << 16) | lz;
    }
    __syncthreads();

    const int mt = wid;
    u32 ahi[8][4], alo[8][4];
#pragma unroll
    for (int ks = 0; ks < 8; ks++) {
        int w = ks * 8 + tid4;
        int ra = (mt * 16 + grp) * 68, rbw = (mt * 16 + grp + 8) * 68;
        ahi[ks][0] = AH[ra + w];  ahi[ks][1] = AH[rbw + w];
        ahi[ks][2] = AH[ra + w + 4]; ahi[ks][3] = AH[rbw + w + 4];
        alo[ks][0] = AL[ra + w];  alo[ks][1] = AL[rbw + w];
        alo[ks][2] = AL[ra + w + 4]; alo[ks][3] = AL[rbw + w + 4];
    }

#pragma unroll 1
    for (int ntp = 0; ntp < 32; ntp++) {
        const int n0 = ntp * 16;
        const __nv_bfloat16* w0p = wih_hi + (n0 + grp) * H_;
        const __nv_bfloat16* w1p = wih_hi + (n0 + 8 + grp) * H_;
        u32 b0h[8][2], b1h[8][2];
#pragma unroll
        for (int ks = 0; ks < 8; ks++) {
            b0h[ks][0] = *(const u32*)(w0p + ks * 16 + tid4 * 2);
            b0h[ks][1] = *(const u32*)(w0p + ks * 16 + tid4 * 2 + 8);
            b1h[ks][0] = *(const u32*)(w1p + ks * 16 + tid4 * 2);
            b1h[ks][1] = *(const u32*)(w1p + ks * 16 + tid4 * 2 + 8);
        }
        float2 bb0 = *(const float2*)&br[n0 + tid4 * 2];
        float2 bb1 = *(const float2*)&br[n0 + 8 + tid4 * 2];
        float D0[4] = {bb0.x, bb0.y, bb0.x, bb0.y};
        float D1[4] = {bb1.x, bb1.y, bb1.x, bb1.y};
#pragma unroll
        for (int ks = 0; ks < 8; ks++) {
            mma16816(D0, ahi[ks], b0h[ks][0], b0h[ks][1]);
            mma16816(D1, ahi[ks], b1h[ks][0], b1h[ks][1]);
        }
        const __nv_bfloat16* l0p = wih_lo + (n0 + grp) * H_;
        const __nv_bfloat16* l1p = wih_lo + (n0 + 8 + grp) * H_;
#pragma unroll
        for (int ks = 0; ks < 8; ks++) {
            u32 x0 = *(const u32*)(l0p + ks * 16 + tid4 * 2);
            u32 x1 = *(const u32*)(l0p + ks * 16 + tid4 * 2 + 8);
            mma16816(D0, ahi[ks], x0, x1);
            u32 y0 = *(const u32*)(l1p + ks * 16 + tid4 * 2);
            u32 y1 = *(const u32*)(l1p + ks * 16 + tid4 * 2 + 8);
            mma16816(D1, ahi[ks], y0, y1);
        }
#pragma unroll
        for (int ks = 0; ks < 8; ks++) {
            mma16816(D0, alo[ks], b0h[ks][0], b0h[ks][1]);
            mma16816(D1, alo[ks], b1h[ks][0], b1h[ks][1]);
        }
        size_t rowA = (r0 + mt * 16 + grp) * G4H;
        size_t rowB = (r0 + mt * 16 + grp + 8) * G4H;
        *(float2*)&g_xp[rowA + n0 + tid4 * 2]     = make_float2(D0[0], D0[1]);
        *(float2*)&g_xp[rowB + n0 + tid4 * 2]     = make_float2(D0[2], D0[3]);
        *(float2*)&g_xp[rowA + n0 + 8 + tid4 * 2] = make_float2(D1[0], D1[1]);
        *(float2*)&g_xp[rowB + n0 + 8 + tid4 * 2] = make_float2(D1[2], D1[3]);
    }
}

// ---------------- GCN ------------------------------------------------------------
__global__ void k_lin1(const float* __restrict__ w) {
    __shared__ float fr[H_];
    int row = blockIdx.x, tid = threadIdx.x;   // 128 threads
    fr[tid] = g_h[((size_t)(T_ - 1) * S_ + row) * H_ + tid];
    __syncthreads();
    const float* wr = w + tid * H_;
    float a = 0.0f;
#pragma unroll 4
    for (int k = 0; k < H_; k++) a = fmaf(fr[k], wr[k], a);
    g_xl1[row * G1_ + tid] = a;
}

__global__ void k_lin2(const float* __restrict__ w) {
    __shared__ float fr[G1_];
    int row = blockIdx.x, tid = threadIdx.x;   // 64 threads
    fr[tid]      = fmaxf(g_h1[row * G1_ + tid], 0.0f);
    fr[tid + 64] = fmaxf(g_h1[row * G1_ + tid + 64], 0.0f);
    __syncthreads();
    const float* wr = w + tid * G1_;
    float a = 0.0f;
#pragma unroll 4
    for (int k = 0; k < G1_; k++) a = fmaf(fr[k], wr[k], a);
    g_xl2[row * G2_ + tid] = a;
}

template <int Gd>
__global__ void k_agg_init(const float* __restrict__ bias) {
    const float* xl = (Gd == G1_) ? g_xl1 : g_xl2;
    float* outb     = (Gd == G1_) ? g_h1  : g_h2;
    int i = blockIdx.x * blockDim.x + threadIdx.x;
    if (i < S_ * Gd) {
        int g = i % Gd;
        int n = (i / Gd) & (N_ - 1);
        float d = g_dis[n];
        outb[i] = bias[g] + xl[i] * d * d;
    }
}

template <int Gd>
__global__ void k_agg_edge(const void* __restrict__ ei) {
    const float* xl = (Gd == G1_) ? g_xl1 : g_xl2;
    float* outb     = (Gd == G1_) ? g_h1  : g_h2;
    int i = blockIdx.x * blockDim.x + threadIdx.x;
    constexpr int per = B_ * Gd;
    if (i >= E_ * per) return;
    int e = i / per;
    int r = i - e * per;
    int b = r / Gd;
    int g = r - b * Gd;
    int is64 = g_is64;
    int src = edge_at(ei, is64, e);
    int dst = edge_at(ei, is64, E_ + e);
    float norm = g_dis[src] * g_dis[dst];
    atomicAdd(&outb[(b * N_ + dst) * Gd + g],
              xl[(b * N_ + src) * Gd + g] * norm);
}

__global__ void k_final(const float* __restrict__ cls_w,
                        const float* __restrict__ cls_b,
                        float* __restrict__ out) {
    int b = blockIdx.x, tid = threadIdx.x;   // 256 threads
    __shared__ float red[256];
    float a = 0.0f;
    for (int i = tid; i < N_ * G2_; i += 256) {
        int g = i & (G2_ - 1);
        a = fmaf(fmaxf(g_h2[b * (N_ * G2_) + i], 0.0f), cls_w[g], a);
    }
    red[tid] = a;
    __syncthreads();
    for (int s = 128; s > 0; s >>= 1) {
        if (tid < s) red[tid] += red[tid + s];
        __syncthreads();
    }
    if (tid == 0) out[b] = red[0] * (1.0f / N_) + cls_b[0];
}

// ---------------- launch ----------------------------------------------------------
extern "C" void kernel_launch(void* const* d_in, const int* in_sizes, int n_in,
                              void* d_out, int out_size) {
    const float* x      = (const float*)d_in[0];
    const void*  ei     = d_in[1];
    const float* w_ih0  = (const float*)d_in[2];
    const float* w_hh0  = (const float*)d_in[3];
    const float* b_ih0  = (const float*)d_in[4];
    const float* b_hh0  = (const float*)d_in[5];
    const float* w_ih1  = (const float*)d_in[6];
    const float* w_hh1  = (const float*)d_in[7];
    const float* b_ih1  = (const float*)d_in[8];
    const float* b_hh1  = (const float*)d_in[9];
    const float* w_ih2  = (const float*)d_in[10];
    const float* w_hh2  = (const float*)d_in[11];
    const float* b_ih2  = (const float*)d_in[12];
    const float* b_hh2  = (const float*)d_in[13];
    const float* gcn1_w = (const float*)d_in[14];
    const float* gcn1_b = (const float*)d_in[15];
    const float* gcn2_w = (const float*)d_in[16];
    const float* gcn2_b = (const float*)d_in[17];
    const float* cls_w  = (const float*)d_in[18];
    const float* cls_b  = (const float*)d_in[19];
    float* out = (float*)d_out;

    __nv_bfloat16 *whh_hi, *whh_lo, *wih_hi, *wih_lo;
    float *br, *w0r;
    cudaGetSymbolAddress((void**)&whh_hi, g_whh_hi);
    cudaGetSymbolAddress((void**)&whh_lo, g_whh_lo);
    cudaGetSymbolAddress((void**)&wih_hi, g_wih_hi);
    cudaGetSymbolAddress((void**)&wih_lo, g_wih_lo);
    cudaGetSymbolAddress((void**)&br, g_br);
    cudaGetSymbolAddress((void**)&w0r, g_w0r);

    static bool attr_set = false;
    if (!attr_set) {
        cudaFuncSetAttribute(proj_mma, cudaFuncAttributeMaxDynamicSharedMemorySize, 69632);
        attr_set = true;
    }

    k_detect<<<1, 512>>>((const int*)ei);

    // weight prep
    constexpr int WN = G4H * H_;
    k_prep_w<<<WN / 256, 256>>>(w_hh0, whh_hi + 0 * WN, whh_lo + 0 * WN);
    k_prep_w<<<WN / 256, 256>>>(w_hh1, whh_hi + 1 * WN, whh_lo + 1 * WN);
    k_prep_w<<<WN / 256, 256>>>(w_hh2, whh_hi + 2 * WN, whh_lo + 2 * WN);
    k_prep_w<<<WN / 256, 256>>>(w_ih1, wih_hi + 0 * WN, wih_lo + 0 * WN);
    k_prep_w<<<WN / 256, 256>>>(w_ih2, wih_hi + 1 * WN, wih_lo + 1 * WN);
    k_prep_b<<<2, 256>>>(b_ih0, b_hh0, br + 0 * G4H);
    k_prep_b<<<2, 256>>>(b_ih1, b_hh1, br + 1 * G4H);
    k_prep_b<<<2, 256>>>(b_ih2, b_hh2, br + 2 * G4H);
    k_prep_w0<<<2, 256>>>(w_ih0, w0r);

    const int RB = S_ / 16;              // 256 blocks
    const int PB = (T_ * S_) / 128;      // 2048 blocks

    // layer 0
    rec_mma<0, 1><<<RB, 256>>>(x, whh_hi + 0 * WN, whh_lo + 0 * WN, w0r, br + 0 * G4H);
    // layer 1
    proj_mma<<<PB, 256, 69632>>>(wih_hi + 0 * WN, wih_lo + 0 * WN, br + 1 * G4H);
    rec_mma<1, 1><<<RB, 256>>>(nullptr, whh_hi + 1 * WN, whh_lo + 1 * WN, nullptr, nullptr);
    // layer 2
    proj_mma<<<PB, 256, 69632>>>(wih_hi + 1 * WN, wih_lo + 1 * WN, br + 2 * G4H);
    rec_mma<1, 0><<<RB, 256>>>(nullptr, whh_hi + 2 * WN, whh_lo + 2 * WN, nullptr, nullptr);

    // GCN
    k_deg<<<(E_ + 255) / 256, 256>>>(ei);
    k_dis<<<2, 256>>>();

    k_lin1<<<S_, 128>>>(gcn1_w);
    k_agg_init<G1_><<<(S_ * G1_ + 255) / 256, 256>>>(gcn1_b);
    k_agg_edge<G1_><<<(E_ * B_ * G1_ + 255) / 256, 256>>>(ei);

    k_lin2<<<S_, 64>>>(gcn2_w);
    k_agg_init<G2_><<<(S_ * G2_ + 255) / 256, 256>>>(gcn2_b);
    k_agg_edge<G2_><<<(E_ * B_ * G2_ + 255) / 256, 256>>>(ei);

    k_final<<<B_, 256>>>(cls_w, cls_b, out);
}

// round 7
// speedup vs baseline: 2.4133x; 2.4133x over previous
#include <cuda_runtime.h>
#include <cuda_fp16.h>

#define DINLINE __device__ __forceinline__
typedef unsigned int u32;
typedef unsigned short u16;

constexpr int B_ = 8, T_ = 64, N_ = 512, H_ = 128, E_ = 8192;
constexpr int S_ = B_ * N_;       // 4096 sequences
constexpr int G1_ = 128, G2_ = 64;
constexpr int G4H = 4 * H_;       // 512 gate rows

// SMEM layouts (byte offsets)
constexpr int WROW   = 272;                    // 136 fp16 per row (128 + pad)
constexpr int OFF_W  = 0;                      // 512*272 = 139264
constexpr int OFF_H  = 139264;                 // [buf][plane] 4 x 8704
constexpr int HPLANE = 32 * WROW;              // 8704
constexpr int OFF_SX = OFF_H + 4 * HPLANE;     // 174080, 8192 bytes
constexpr int REC_SM = OFF_SX + 64 * 32 * 4;   // 182272

constexpr int OFF_AH = 139264;                 // proj: A hi plane 128*272
constexpr int APLANE = 128 * WROW;             // 34816
constexpr int OFF_AL = OFF_AH + APLANE;
constexpr int PROJ_SM = OFF_AL + APLANE;       // 208896

// ---------------- device scratch (static globals; no allocation) -------------
__device__ float g_h [(size_t)T_ * S_ * H_];     // [t*S+s][j]    128 MiB
__device__ float g_xp[(size_t)T_ * S_ * G4H];    // [t*S+s][4j+g] 512 MiB
__device__ u32   g_whh_h[3][G4H * 64];           // permuted fp16-pair W_hh
__device__ u32   g_wih_h[2][G4H * 64];           // permuted fp16-pair W_ih
__device__ float g_br[3][G4H];                   // b_ih+b_hh permuted (4j+g)
__device__ float g_w0r[G4H];                     // w_ih0 permuted
__device__ float g_xl1[S_ * G1_];
__device__ float g_h1[S_ * G1_];
__device__ float g_xl2[S_ * G2_];
__device__ float g_h2[S_ * G2_];
__device__ float g_deg[N_];
__device__ float g_dis[N_];
__device__ int   g_is64;

// ---------------- helpers ------------------------------------------------------
DINLINE float sigf(float x)  { return __fdividef(1.0f, 1.0f + __expf(-x)); }
DINLINE float tanh_(float x) { return __fdividef(2.0f, 1.0f + __expf(-2.0f * x)) - 1.0f; }

DINLINE u32 smem_u32(const void* p) {
    u32 a;
    asm("{ .reg .u64 t; cvta.to.shared.u64 t, %1; cvt.u32.u64 %0, t; }" : "=r"(a) : "l"(p));
    return a;
}

DINLINE void mma_f16(float* D, const u32* A, u32 b0, u32 b1) {
    asm("mma.sync.aligned.m16n8k16.row.col.f32.f16.f16.f32 "
        "{%0,%1,%2,%3},{%4,%5,%6,%7},{%8,%9},{%0,%1,%2,%3};"
        : "+f"(D[0]), "+f"(D[1]), "+f"(D[2]), "+f"(D[3])
        : "r"(A[0]), "r"(A[1]), "r"(A[2]), "r"(A[3]), "r"(b0), "r"(b1));
}

#define LDSM4(R, ADDR) \
    asm volatile("ldmatrix.sync.aligned.m8n8.x4.shared.b16 {%0,%1,%2,%3},[%4];" \
        : "=r"((R)[0]), "=r"((R)[1]), "=r"((R)[2]), "=r"((R)[3]) : "r"(ADDR))

DINLINE u32 packh(float a, float b) {
    __half2 h = __floats2half2_rn(a, b);
    return *(u32*)&h;
}

// ---------------- edge dtype detection + degree init ---------------------------
__global__ void k_detect(const int* __restrict__ ei32) {
    __shared__ int nz;
    int tid = threadIdx.x;
    if (tid == 0) nz = 0;
    if (tid < N_) g_deg[tid] = 1.0f;
    __syncthreads();
    int acc = 0;
    for (int i = 1 + 2 * tid; i < 2 * E_; i += 2 * blockDim.x) acc |= ei32[i];
    if (acc) atomicOr(&nz, 1);
    __syncthreads();
    if (tid == 0) g_is64 = (nz == 0) ? 1 : 0;
}

DINLINE int edge_at(const void* p, int is64, int idx) {
    return is64 ? (int)((const long long*)p)[idx] : ((const int*)p)[idx];
}

__global__ void k_deg(const void* __restrict__ ei) {
    int e = blockIdx.x * blockDim.x + threadIdx.x;
    if (e < E_) atomicAdd(&g_deg[edge_at(ei, g_is64, E_ + e)], 1.0f);
}

__global__ void k_dis() {
    int n = blockIdx.x * blockDim.x + threadIdx.x;
    if (n < N_) g_dis[n] = rsqrtf(g_deg[n]);
}

// ---------------- weight prep: permute rows (4j+g), fp16-pair pack -------------
__global__ void k_prep_w(const float* __restrict__ w, u32* __restrict__ outw) {
    int i = blockIdx.x * blockDim.x + threadIdx.x;   // 512*64
    int colp = i >> 6, kp = i & 63;
    int j = colp >> 2, g = colp & 3;
    const float* wr = w + (g * H_ + j) * H_ + 2 * kp;
    outw[i] = packh(wr[0], wr[1]);
}

__global__ void k_prep_b(const float* __restrict__ bi, const float* __restrict__ bh,
                         float* __restrict__ outb) {
    int colp = blockIdx.x * blockDim.x + threadIdx.x;
    if (colp < G4H) {
        int j = colp >> 2, g = colp & 3;
        outb[colp] = bi[g * H_ + j] + bh[g * H_ + j];
    }
}

__global__ void k_prep_w0(const float* __restrict__ w, float* __restrict__ outw) {
    int colp = blockIdx.x * blockDim.x + threadIdx.x;
    if (colp < G4H) {
        int j = colp >> 2, g = colp & 3;
        outw[colp] = w[g * H_ + j];
    }
}

// ---------------- tensor-core LSTM recurrence -----------------------------------
// Block: 32 seqs, 8 warps; warp owns 64 gate-cols. W fp16 in SMEM (ldmatrix),
// h fp16 hi+lo in SMEM (2-term MMA). 128 blocks.
template <int MODE, int WRITE_ALL>
__global__ void __launch_bounds__(256, 1) rec_mma(
    const float* __restrict__ x,               // MODE 0
    const u32* __restrict__ w_h,               // [512][64] fp16 pairs
    const float* __restrict__ w0r,             // MODE 0
    const float* __restrict__ br0)             // MODE 0
{
    extern __shared__ __align__(16) char sm[];
    const u32 sbase = smem_u32(sm);

    const int tid = threadIdx.x, wid = tid >> 5, lane = tid & 31;
    const int grp = lane >> 2, tid4 = lane & 3;
    const bool evn = (tid4 & 1) == 0;
    const int s0 = blockIdx.x * 32;

    // load W into SMEM (once)
    for (int i = tid; i < 512 * 64; i += 256) {
        int r = i >> 6, c = i & 63;
        *(u32*)(sm + OFF_W + r * WROW + c * 4) = w_h[i];
    }
    // zero h buffer 0 (hi+lo contiguous)
    for (int i = tid; i < 2 * HPLANE / 4; i += 256)
        ((u32*)(sm + OFF_H))[i] = 0;
    // stage x (MODE 0)
    if (MODE == 0) {
        float* sx = (float*)(sm + OFF_SX);
        for (int i = tid; i < 64 * 32; i += 256) {
            int t = i >> 5, m = i & 31;
            int s = s0 + m;
            sx[t * 32 + m] = x[(s >> 9) * (T_ * N_) + t * N_ + (s & (N_ - 1))];
        }
    }
    __syncthreads();

    // ldmatrix lane offsets
    const int qa = lane >> 3;
    const int a_loff = ((lane & 7) + (qa & 1) * 8) * WROW + ((qa >> 1) * 8) * 2;  // A-frag
    const int b_loff = (lane & 7) * WROW + qa * 16;                               // B-frag (+row n0)

    float c_st[16];
#pragma unroll
    for (int q = 0; q < 16; q++) c_st[q] = 0.0f;

    const float* sxf = (const float*)(sm + OFF_SX);

    for (int t = 0; t < T_; t++) {
        const int rb = t & 1, wb = rb ^ 1;
        const u32 hhi = sbase + OFF_H + (rb * 2 + 0) * HPLANE;
        const u32 hlo = sbase + OFF_H + (rb * 2 + 1) * HPLANE;
        const u32 whi = sbase + OFF_H + (wb * 2 + 0) * HPLANE;
        const u32 wlo = sbase + OFF_H + (wb * 2 + 1) * HPLANE;

#pragma unroll
        for (int mt = 0; mt < 2; mt++) {
            // A fragments (h hi+lo) for this m-tile
            u32 ahi[8][4], alo[8][4];
            const u32 abase_h = hhi + mt * 16 * WROW + a_loff;
            const u32 abase_l = hlo + mt * 16 * WROW + a_loff;
#pragma unroll
            for (int ks = 0; ks < 8; ks++) {
                LDSM4(ahi[ks], abase_h + ks * 32);
                LDSM4(alo[ks], abase_l + ks * 32);
            }

            // prefetch input contribution for this m-tile
            float2 xpA[8], xpB[8];
            if (MODE == 1) {
                const float* xpb = g_xp + ((size_t)t * S_ + s0 + mt * 16) * G4H;
#pragma unroll
                for (int nt = 0; nt < 8; nt++) {
                    int c0 = wid * 64 + nt * 8 + tid4 * 2;
                    xpA[nt] = *(const float2*)&xpb[grp * G4H + c0];
                    xpB[nt] = *(const float2*)&xpb[(grp + 8) * G4H + c0];
                }
            }
            float xA = 0.f, xB = 0.f;
            if (MODE == 0) {
                xA = sxf[t * 32 + mt * 16 + grp];
                xB = sxf[t * 32 + mt * 16 + grp + 8];
            }

#pragma unroll
            for (int nt = 0; nt < 8; nt++) {
                const int n0 = wid * 64 + nt * 8;
                u32 bb[8][2];
#pragma unroll
                for (int kc = 0; kc < 4; kc++) {
                    u32 r[4];
                    LDSM4(r, sbase + OFF_W + n0 * WROW + b_loff + kc * 64);
                    bb[kc * 2][0] = r[0]; bb[kc * 2][1] = r[1];
                    bb[kc * 2 + 1][0] = r[2]; bb[kc * 2 + 1][1] = r[3];
                }
                float D[4] = {0, 0, 0, 0};
#pragma unroll
                for (int ks = 0; ks < 8; ks++) mma_f16(D, ahi[ks], bb[ks][0], bb[ks][1]);
#pragma unroll
                for (int ks = 0; ks < 8; ks++) mma_f16(D, alo[ks], bb[ks][0], bb[ks][1]);

                if (MODE == 0) {
                    int c0 = n0 + tid4 * 2;
                    float2 w0 = *(const float2*)&w0r[c0];
                    float2 bbv = *(const float2*)&br0[c0];
                    D[0] += xA * w0.x + bbv.x; D[1] += xA * w0.y + bbv.y;
                    D[2] += xB * w0.x + bbv.x; D[3] += xB * w0.y + bbv.y;
                } else {
                    D[0] += xpA[nt].x; D[1] += xpA[nt].y;
                    D[2] += xpB[nt].x; D[3] += xpB[nt].y;
                }

                // gate fold via lane-pair shuffle (validated in R5)
                float sv0 = evn ? D[2] : D[0];
                float rr0 = __shfl_xor_sync(0xffffffffu, sv0, 1);
                float sv1 = evn ? D[3] : D[1];
                float rr1 = __shfl_xor_sync(0xffffffffu, sv1, 1);
                float pi = evn ? D[0] : rr0;
                float pf = evn ? D[1] : rr1;
                float pg = evn ? rr0 : D[2];
                float po = evn ? rr1 : D[3];
                const int ci = mt * 8 + nt;
                float cn = sigf(pf) * c_st[ci] + sigf(pi) * tanh_(pg);
                c_st[ci] = cn;
                float hv = sigf(po) * tanh_(cn);
                const int myrow = mt * 16 + (evn ? grp : grp + 8);
                const int j = wid * 16 + nt * 2 + (tid4 >> 1);
                __half hh = __float2half_rn(hv);
                __half hl = __float2half_rn(hv - __half2float(hh));
                *(__half*)(sm + (whi - sbase) + myrow * WROW + j * 2) = hh;
                *(__half*)(sm + (wlo - sbase) + myrow * WROW + j * 2) = hl;
                if (WRITE_ALL || t == T_ - 1)
                    g_h[((size_t)t * S_ + s0 + myrow) * H_ + j] = hv;
            }
        }
        __syncthreads();
    }
}

// ---------------- tensor-core input projection (persistent) ---------------------
// g_xp[row][col'] = h_prev[row] . W_ih[col'] + bias. Grid 148, 8 warps/block.
__global__ void __launch_bounds__(256, 1) proj_mma(
    const u32* __restrict__ w_h,
    const float* __restrict__ br)
{
    extern __shared__ __align__(16) char sm[];
    const u32 sbase = smem_u32(sm);

    const int tid = threadIdx.x, wid = tid >> 5, lane = tid & 31;
    const int grp = lane >> 2, tid4 = lane & 3;

    for (int i = tid; i < 512 * 64; i += 256) {
        int r = i >> 6, c = i & 63;
        *(u32*)(sm + OFF_W + r * WROW + c * 4) = w_h[i];
    }

    const int qa = lane >> 3;
    const int a_loff = ((lane & 7) + (qa & 1) * 8) * WROW + ((qa >> 1) * 8) * 2;
    const int b_loff = (lane & 7) * WROW + qa * 16;

    const int ntiles = (T_ * S_) / 128;   // 2048
    for (int rt = blockIdx.x; rt < ntiles; rt += gridDim.x) {
        __syncthreads();
        // stage + split h tile (128 rows x 128 k)
        const float2* src = (const float2*)(g_h + (size_t)rt * 128 * H_);
        for (int i = tid; i < 128 * 64; i += 256) {
            int row = i >> 6, kp = i & 63;
            float2 v = src[i];
            __half hx = __float2half_rn(v.x), hy = __float2half_rn(v.y);
            u32 hip = ((u32)*(u16*)&hy << 16) | *(u16*)&hx;
            __half lx = __float2half_rn(v.x - __half2float(hx));
            __half ly = __float2half_rn(v.y - __half2float(hy));
            u32 lop = ((u32)*(u16*)&ly << 16) | *(u16*)&lx;
            *(u32*)(sm + OFF_AH + row * WROW + kp * 4) = hip;
            *(u32*)(sm + OFF_AL + row * WROW + kp * 4) = lop;
        }
        __syncthreads();

        const int mt = wid;
        u32 ahi[8][4], alo[8][4];
        const u32 abase_h = sbase + OFF_AH + mt * 16 * WROW + a_loff;
        const u32 abase_l = sbase + OFF_AL + mt * 16 * WROW + a_loff;
#pragma unroll
        for (int ks = 0; ks < 8; ks++) {
            LDSM4(ahi[ks], abase_h + ks * 32);
            LDSM4(alo[ks], abase_l + ks * 32);
        }

#pragma unroll 2
        for (int nt = 0; nt < 64; nt++) {
            const int n0 = nt * 8;
            u32 bb[8][2];
#pragma unroll
            for (int kc = 0; kc < 4; kc++) {
                u32 r[4];
                LDSM4(r, sbase + OFF_W + n0 * WROW + b_loff + kc * 64);
                bb[kc * 2][0] = r[0]; bb[kc * 2][1] = r[1];
                bb[kc * 2 + 1][0] = r[2]; bb[kc * 2 + 1][1] = r[3];
            }
            float2 bbv = *(const float2*)&br[n0 + tid4 * 2];
            float D[4] = {bbv.x, bbv.y, bbv.x, bbv.y};
#pragma unroll
            for (int ks = 0; ks < 8; ks++) mma_f16(D, ahi[ks], bb[ks][0], bb[ks][1]);
#pragma unroll
            for (int ks = 0; ks < 8; ks++) mma_f16(D, alo[ks], bb[ks][0], bb[ks][1]);

            size_t rowA = ((size_t)rt * 128 + mt * 16 + grp) * G4H;
            size_t rowB = rowA + 8 * G4H;
            *(float2*)&g_xp[rowA + n0 + tid4 * 2] = make_float2(D[0], D[1]);
            *(float2*)&g_xp[rowB + n0 + tid4 * 2] = make_float2(D[2], D[3]);
        }
    }
}

// ---------------- GCN ------------------------------------------------------------
__global__ void k_lin1(const float* __restrict__ w) {
    __shared__ float fr[H_];
    int row = blockIdx.x, tid = threadIdx.x;
    fr[tid] = g_h[((size_t)(T_ - 1) * S_ + row) * H_ + tid];
    __syncthreads();
    const float* wr = w + tid * H_;
    float a = 0.0f;
#pragma unroll 4
    for (int k = 0; k < H_; k++) a = fmaf(fr[k], wr[k], a);
    g_xl1[row * G1_ + tid] = a;
}

__global__ void k_lin2(const float* __restrict__ w) {
    __shared__ float fr[G1_];
    int row = blockIdx.x, tid = threadIdx.x;
    fr[tid]      = fmaxf(g_h1[row * G1_ + tid], 0.0f);
    fr[tid + 64] = fmaxf(g_h1[row * G1_ + tid + 64], 0.0f);
    __syncthreads();
    const float* wr = w + tid * G1_;
    float a = 0.0f;
#pragma unroll 4
    for (int k = 0; k < G1_; k++) a = fmaf(fr[k], wr[k], a);
    g_xl2[row * G2_ + tid] = a;
}

template <int Gd>
__global__ void k_agg_init(const float* __restrict__ bias) {
    const float* xl = (Gd == G1_) ? g_xl1 : g_xl2;
    float* outb     = (Gd == G1_) ? g_h1  : g_h2;
    int i = blockIdx.x * blockDim.x + threadIdx.x;
    if (i < S_ * Gd) {
        int g = i % Gd;
        int n = (i / Gd) & (N_ - 1);
        float d = g_dis[n];
        outb[i] = bias[g] + xl[i] * d * d;
    }
}

template <int Gd>
__global__ void k_agg_edge(const void* __restrict__ ei) {
    const float* xl = (Gd == G1_) ? g_xl1 : g_xl2;
    float* outb     = (Gd == G1_) ? g_h1  : g_h2;
    int i = blockIdx.x * blockDim.x + threadIdx.x;
    constexpr int per = B_ * Gd;
    if (i >= E_ * per) return;
    int e = i / per;
    int r = i - e * per;
    int b = r / Gd;
    int g = r - b * Gd;
    int is64 = g_is64;
    int src = edge_at(ei, is64, e);
    int dst = edge_at(ei, is64, E_ + e);
    float norm = g_dis[src] * g_dis[dst];
    atomicAdd(&outb[(b * N_ + dst) * Gd + g],
              xl[(b * N_ + src) * Gd + g] * norm);
}

__global__ void k_final(const float* __restrict__ cls_w,
                        const float* __restrict__ cls_b,
                        float* __restrict__ out) {
    int b = blockIdx.x, tid = threadIdx.x;
    __shared__ float red[256];
    float a = 0.0f;
    for (int i = tid; i < N_ * G2_; i += 256) {
        int g = i & (G2_ - 1);
        a = fmaf(fmaxf(g_h2[b * (N_ * G2_) + i], 0.0f), cls_w[g], a);
    }
    red[tid] = a;
    __syncthreads();
    for (int s = 128; s > 0; s >>= 1) {
        if (tid < s) red[tid] += red[tid + s];
        __syncthreads();
    }
    if (tid == 0) out[b] = red[0] * (1.0f / N_) + cls_b[0];
}

// ---------------- launch ----------------------------------------------------------
extern "C" void kernel_launch(void* const* d_in, const int* in_sizes, int n_in,
                              void* d_out, int out_size) {
    const float* x      = (const float*)d_in[0];
    const void*  ei     = d_in[1];
    const float* w_ih0  = (const float*)d_in[2];
    const float* w_hh0  = (const float*)d_in[3];
    const float* b_ih0  = (const float*)d_in[4];
    const float* b_hh0  = (const float*)d_in[5];
    const float* w_ih1  = (const float*)d_in[6];
    const float* w_hh1  = (const float*)d_in[7];
    const float* b_ih1  = (const float*)d_in[8];
    const float* b_hh1  = (const float*)d_in[9];
    const float* w_ih2  = (const float*)d_in[10];
    const float* w_hh2  = (const float*)d_in[11];
    const float* b_ih2  = (const float*)d_in[12];
    const float* b_hh2  = (const float*)d_in[13];
    const float* gcn1_w = (const float*)d_in[14];
    const float* gcn1_b = (const float*)d_in[15];
    const float* gcn2_w = (const float*)d_in[16];
    const float* gcn2_b = (const float*)d_in[17];
    const float* cls_w  = (const float*)d_in[18];
    const float* cls_b  = (const float*)d_in[19];
    float* out = (float*)d_out;

    u32 *whh, *wih;
    float *br, *w0r;
    cudaGetSymbolAddress((void**)&whh, g_whh_h);
    cudaGetSymbolAddress((void**)&wih, g_wih_h);
    cudaGetSymbolAddress((void**)&br, g_br);
    cudaGetSymbolAddress((void**)&w0r, g_w0r);

    cudaFuncSetAttribute(rec_mma<0, 1>, cudaFuncAttributeMaxDynamicSharedMemorySize, REC_SM);
    cudaFuncSetAttribute(rec_mma<1, 1>, cudaFuncAttributeMaxDynamicSharedMemorySize, REC_SM);
    cudaFuncSetAttribute(rec_mma<1, 0>, cudaFuncAttributeMaxDynamicSharedMemorySize, REC_SM);
    cudaFuncSetAttribute(proj_mma, cudaFuncAttributeMaxDynamicSharedMemorySize, PROJ_SM);

    k_detect<<<1, 512>>>((const int*)ei);

    constexpr int WN = G4H * 64;
    k_prep_w<<<WN / 256, 256>>>(w_hh0, whh + 0 * WN);
    k_prep_w<<<WN / 256, 256>>>(w_hh1, whh + 1 * WN);
    k_prep_w<<<WN / 256, 256>>>(w_hh2, whh + 2 * WN);
    k_prep_w<<<WN / 256, 256>>>(w_ih1, wih + 0 * WN);
    k_prep_w<<<WN / 256, 256>>>(w_ih2, wih + 1 * WN);
    k_prep_b<<<2, 256>>>(b_ih0, b_hh0, br + 0 * G4H);
    k_prep_b<<<2, 256>>>(b_ih1, b_hh1, br + 1 * G4H);
    k_prep_b<<<2, 256>>>(b_ih2, b_hh2, br + 2 * G4H);
    k_prep_w0<<<2, 256>>>(w_ih0, w0r);

    const int RB = S_ / 32;   // 128 blocks

    // layer 0
    rec_mma<0, 1><<<RB, 256, REC_SM>>>(x, whh + 0 * WN, w0r, br + 0 * G4H);
    // layer 1
    proj_mma<<<148, 256, PROJ_SM>>>(wih + 0 * WN, br + 1 * G4H);
    rec_mma<1, 1><<<RB, 256, REC_SM>>>(nullptr, whh + 1 * WN, nullptr, nullptr);
    // layer 2
    proj_mma<<<148, 256, PROJ_SM>>>(wih + 1 * WN, br + 2 * G4H);
    rec_mma<1, 0><<<RB, 256, REC_SM>>>(nullptr, whh + 2 * WN, nullptr, nullptr);

    // GCN
    k_deg<<<(E_ + 255) / 256, 256>>>(ei);
    k_dis<<<2, 256>>>();

    k_lin1<<<S_, 128>>>(gcn1_w);
    k_agg_init<G1_><<<(S_ * G1_ + 255) / 256, 256>>>(gcn1_b);
    k_agg_edge<G1_><<<(E_ * B_ * G1_ + 255) / 256, 256>>>(ei);

    k_lin2<<<S_, 64>>>(gcn2_w);
    k_agg_init<G2_><<<(S_ * G2_ + 255) / 256, 256>>>(gcn2_b);
    k_agg_edge<G2_><<<(E_ * B_ * G2_ + 255) / 256, 256>>>(ei);

    k_final<<<B_, 256>>>(cls_w, cls_b, out);
}

// round 8
// speedup vs baseline: 4.1433x; 1.7169x over previous
#include <cuda_runtime.h>
#include <cuda_fp16.h>

#define DINLINE __device__ __forceinline__
typedef unsigned int u32;
typedef unsigned short u16;

constexpr int B_ = 8, T_ = 64, N_ = 512, H_ = 128, E_ = 8192;
constexpr int S_ = B_ * N_;       // 4096 sequences
constexpr int G1_ = 128, G2_ = 64;
constexpr int G4H = 4 * H_;       // 512 gate rows

// ---------------- SMEM layout (byte offsets) -----------------------------------
constexpr int WROW    = 272;                   // 136 fp16 per row (128 + 8 pad)
constexpr int OFF_W   = 0;                     // 512*272 = 139264
constexpr int OFF_H   = 139264;                // h hi plane (32 x 272)
constexpr int HPLANE  = 32 * WROW;             // 8704
constexpr int OFF_HL  = OFF_H + HPLANE;        // h lo plane
constexpr int OFF_XP  = OFF_HL + HPLANE;       // 156672: xp staging (MODE 1)
constexpr int XPROW   = 2064;                  // 512 floats + 16B pad
constexpr int REC_SM  = OFF_XP + 32 * XPROW;   // 222720
// MODE 0 reuse of the XP region:
constexpr int OFF_SX  = OFF_XP;                // 64*32 fp32 = 8192
constexpr int OFF_W0S = OFF_SX + 8192;         // 512 fp32
constexpr int OFF_BRS = OFF_W0S + 2048;        // 512 fp32

constexpr int OFF_AH  = 139264;                // proj: A hi plane 128*272
constexpr int APLANE  = 128 * WROW;            // 34816
constexpr int OFF_AL  = OFF_AH + APLANE;
constexpr int PROJ_SM = OFF_AL + APLANE;       // 208896

// ---------------- device scratch (static globals; no allocation) ---------------
__device__ float g_h [(size_t)T_ * S_ * H_];     // [t*S+s][j]    128 MiB
__device__ float g_xp[(size_t)T_ * S_ * G4H];    // [t*S+s][4j+g] 512 MiB
__device__ u32   g_whh_h[3][G4H * 64];           // permuted fp16-pair W_hh
__device__ u32   g_wih_h[2][G4H * 64];           // permuted fp16-pair W_ih
__device__ float g_br[3][G4H];                   // b_ih+b_hh permuted (4j+g)
__device__ float g_w0r[G4H];                     // w_ih0 permuted
__device__ float g_xl1[S_ * G1_];
__device__ float g_h1[S_ * G1_];
__device__ float g_xl2[S_ * G2_];
__device__ float g_h2[S_ * G2_];
__device__ float g_deg[N_];
__device__ float g_dis[N_];
__device__ int   g_is64;

// ---------------- helpers -------------------------------------------------------
DINLINE float clamp14(float x) { return fminf(fmaxf(x, -14.0f), 14.0f); }

DINLINE u32 smem_u32(const void* p) {
    u32 a;
    asm("{ .reg .u64 t; cvta.to.shared.u64 t, %1; cvt.u32.u64 %0, t; }" : "=r"(a) : "l"(p));
    return a;
}

DINLINE void mma_f16(float* D, const u32* A, u32 b0, u32 b1) {
    asm("mma.sync.aligned.m16n8k16.row.col.f32.f16.f16.f32 "
        "{%0,%1,%2,%3},{%4,%5,%6,%7},{%8,%9},{%0,%1,%2,%3};"
        : "+f"(D[0]), "+f"(D[1]), "+f"(D[2]), "+f"(D[3])
        : "r"(A[0]), "r"(A[1]), "r"(A[2]), "r"(A[3]), "r"(b0), "r"(b1));
}

#define LDSM4(R, ADDR) \
    asm volatile("ldmatrix.sync.aligned.m8n8.x4.shared.b16 {%0,%1,%2,%3},[%4];" \
        : "=r"((R)[0]), "=r"((R)[1]), "=r"((R)[2]), "=r"((R)[3]) : "r"(ADDR))

DINLINE void cp_async16(u32 dst, const void* src) {
    asm volatile("cp.async.cg.shared.global [%0], [%1], 16;" :: "r"(dst), "l"(src) : "memory");
}
#define CP_COMMIT() asm volatile("cp.async.commit_group;" ::: "memory")
#define CP_WAIT0()  asm volatile("cp.async.wait_group 0;" ::: "memory")

DINLINE u32 packh(float a, float b) {
    __half2 h = __floats2half2_rn(a, b);
    return *(u32*)&h;
}

// ---------------- edge dtype detection + degree init ----------------------------
__global__ void k_detect(const int* __restrict__ ei32) {
    __shared__ int nz;
    int tid = threadIdx.x;
    if (tid == 0) nz = 0;
    if (tid < N_) g_deg[tid] = 1.0f;
    __syncthreads();
    int acc = 0;
    for (int i = 1 + 2 * tid; i < 2 * E_; i += 2 * blockDim.x) acc |= ei32[i];
    if (acc) atomicOr(&nz, 1);
    __syncthreads();
    if (tid == 0) g_is64 = (nz == 0) ? 1 : 0;
}

DINLINE int edge_at(const void* p, int is64, int idx) {
    return is64 ? (int)((const long long*)p)[idx] : ((const int*)p)[idx];
}

__global__ void k_deg(const void* __restrict__ ei) {
    int e = blockIdx.x * blockDim.x + threadIdx.x;
    if (e < E_) atomicAdd(&g_deg[edge_at(ei, g_is64, E_ + e)], 1.0f);
}

__global__ void k_dis() {
    int n = blockIdx.x * blockDim.x + threadIdx.x;
    if (n < N_) g_dis[n] = rsqrtf(g_deg[n]);
}

// ---------------- weight prep: permute rows (4j+g), fp16-pair pack --------------
__global__ void k_prep_w(const float* __restrict__ w, u32* __restrict__ outw) {
    int i = blockIdx.x * blockDim.x + threadIdx.x;   // 512*64
    int colp = i >> 6, kp = i & 63;
    int j = colp >> 2, g = colp & 3;
    const float* wr = w + (g * H_ + j) * H_ + 2 * kp;
    outw[i] = packh(wr[0], wr[1]);
}

__global__ void k_prep_b(const float* __restrict__ bi, const float* __restrict__ bh,
                         float* __restrict__ outb) {
    int colp = blockIdx.x * blockDim.x + threadIdx.x;
    if (colp < G4H) {
        int j = colp >> 2, g = colp & 3;
        outb[colp] = bi[g * H_ + j] + bh[g * H_ + j];
    }
}

__global__ void k_prep_w0(const float* __restrict__ w, float* __restrict__ outw) {
    int colp = blockIdx.x * blockDim.x + threadIdx.x;
    if (colp < G4H) {
        int j = colp >> 2, g = colp & 3;
        outw[colp] = w[g * H_ + j];
    }
}

// ---------------- MMA chain for one 16x8 n-tile ----------------------------------
DINLINE void mma_chain(float* D, int n0, u32 sbase, int b_loff,
                       const u32 (*ahi)[4], const u32 (*alo)[4]) {
    u32 bb[8][2];
#pragma unroll
    for (int kc = 0; kc < 4; kc++) {
        u32 r[4];
        LDSM4(r, sbase + OFF_W + n0 * WROW + b_loff + kc * 64);
        bb[kc * 2][0] = r[0]; bb[kc * 2][1] = r[1];
        bb[kc * 2 + 1][0] = r[2]; bb[kc * 2 + 1][1] = r[3];
    }
    D[0] = D[1] = D[2] = D[3] = 0.0f;
#pragma unroll
    for (int ks = 0; ks < 8; ks++) mma_f16(D, ahi[ks], bb[ks][0], bb[ks][1]);
#pragma unroll
    for (int ks = 0; ks < 8; ks++) mma_f16(D, alo[ks], bb[ks][0], bb[ks][1]);
}

// ---------------- gate fold: shuffle, input add, activations, h write ------------
template <int MODE>
DINLINE void gate_fold(float* D, float& c_ref, char* sm, bool evn,
                       int myrow, int j, int t) {
    float sv0 = evn ? D[2] : D[0];
    float rr0 = __shfl_xor_sync(0xffffffffu, sv0, 1);
    float sv1 = evn ? D[3] : D[1];
    float rr1 = __shfl_xor_sync(0xffffffffu, sv1, 1);
    float pi = evn ? D[0] : rr0;
    float pf = evn ? D[1] : rr1;
    float pg = evn ? rr0 : D[2];
    float po = evn ? rr1 : D[3];

    if (MODE == 1) {
        float4 xq = *(const float4*)(sm + OFF_XP + myrow * XPROW + j * 16);
        pi += xq.x; pf += xq.y; pg += xq.z; po += xq.w;
    } else {
        float xv = ((const float*)(sm + OFF_SX))[t * 32 + myrow];
        float4 w4 = ((const float4*)(sm + OFF_W0S))[j];
        float4 b4 = ((const float4*)(sm + OFF_BRS))[j];
        pi += xv * w4.x + b4.x;
        pf += xv * w4.y + b4.y;
        pg += xv * w4.z + b4.z;
        po += xv * w4.w + b4.w;
    }
    pi = clamp14(pi); pf = clamp14(pf); pg = clamp14(pg); po = clamp14(po);

    // cn = sig(pf)*c + sig(pi)*tanh(pg) with one reciprocal
    float ea = __expf(-pf);
    float eb = __expf(-pi);
    float G  = __expf(2.0f * pg);
    float t1 = (1.0f + eb) * (G + 1.0f);
    float cn = __fdividef(c_ref * t1 + (G - 1.0f) * (1.0f + ea),
                          (1.0f + ea) * t1);
    c_ref = cn;
    // hv = sig(po)*tanh(cn) with one reciprocal
    float ed = __expf(-po);
    float Hc = __expf(2.0f * clamp14(cn));
    float hv = __fdividef(Hc - 1.0f, (1.0f + ed) * (Hc + 1.0f));

    __half hh = __float2half_rn(hv);
    __half hl = __float2half_rn(hv - __half2float(hh));
    *(__half*)(sm + OFF_H  + myrow * WROW + j * 2) = hh;
    *(__half*)(sm + OFF_HL + myrow * WROW + j * 2) = hl;
}

// ---------------- tensor-core LSTM recurrence ------------------------------------
// 512 threads, 16 warps: mt = wid&1 (row half), cw = wid>>1 (64 gate cols).
// W fp16 SMEM-resident; h single-buffered in-place (hi+lo planes);
// xp staged via cp.async per step (MODE 1).
template <int MODE, int WRITE_ALL>
__global__ void __launch_bounds__(512, 1) rec_mma(
    const float* __restrict__ x,               // MODE 0
    const u32* __restrict__ w_h,               // [512][64] fp16 pairs
    const float* __restrict__ w0r,             // MODE 0
    const float* __restrict__ br0)             // MODE 0
{
    extern __shared__ __align__(16) char sm[];
    const u32 sbase = smem_u32(sm);

    const int tid = threadIdx.x, wid = tid >> 5, lane = tid & 31;
    const int grp = lane >> 2, tid4 = lane & 3;
    const bool evn = (tid4 & 1) == 0;
    const int mt = wid & 1, cw = wid >> 1;
    const int s0 = blockIdx.x * 32;

    // load W (once)
    for (int i = tid; i < 512 * 64; i += 512) {
        int r = i >> 6, c = i & 63;
        *(u32*)(sm + OFF_W + r * WROW + c * 4) = w_h[i];
    }
    // zero h planes
    for (int i = tid; i < 2 * HPLANE / 4; i += 512)
        ((u32*)(sm + OFF_H))[i] = 0;
    if (MODE == 0) {
        float* sx = (float*)(sm + OFF_SX);
        for (int i = tid; i < 64 * 32; i += 512) {
            int t = i >> 5, m = i & 31;
            int s = s0 + m;
            sx[i] = x[(s >> 9) * (T_ * N_) + t * N_ + (s & (N_ - 1))];
        }
        if (tid < 512) {
            ((float*)(sm + OFF_W0S))[tid] = w0r[tid];
            ((float*)(sm + OFF_BRS))[tid] = br0[tid];
        }
    }
    __syncthreads();

    const int qa = lane >> 3;
    const int a_loff = ((lane & 7) + (qa & 1) * 8) * WROW + ((qa >> 1) * 8) * 2;
    const int b_loff = (lane & 7) * WROW + qa * 16;
    const u32 a_hi = sbase + OFF_H  + mt * 16 * WROW + a_loff;
    const u32 a_lo = sbase + OFF_HL + mt * 16 * WROW + a_loff;
    const int myrow = mt * 16 + (evn ? grp : grp + 8);

    float c_st[8];
#pragma unroll
    for (int q = 0; q < 8; q++) c_st[q] = 0.0f;

    for (int t = 0; t < T_; t++) {
        // stage xp[t] via cp.async (32 rows x 2048B)
        if (MODE == 1) {
#pragma unroll
            for (int q = 0; q < 8; q++) {
                int chunk = q * 512 + tid;
                int r = chunk >> 7, c16 = chunk & 127;
                cp_async16(sbase + OFF_XP + r * XPROW + c16 * 16,
                           g_xp + ((size_t)t * S_ + s0 + r) * G4H + c16 * 4);
            }
            CP_COMMIT();
        }

        // A fragments (h hi+lo) for my mt
        u32 ahi[8][4], alo[8][4];
#pragma unroll
        for (int ks = 0; ks < 8; ks++) {
            LDSM4(ahi[ks], a_hi + ks * 32);
            LDSM4(alo[ks], a_lo + ks * 32);
        }

        float D[4][4];
#pragma unroll
        for (int nt = 0; nt < 4; nt++)
            mma_chain(D[nt], cw * 64 + nt * 8, sbase, b_loff, ahi, alo);

        if (MODE == 1) CP_WAIT0();
        __syncthreads();   // all A-reads done everywhere; xp visible

#pragma unroll
        for (int nt = 0; nt < 4; nt++)
            gate_fold<MODE>(D[nt], c_st[nt], sm, evn, myrow,
                            cw * 16 + nt * 2 + (tid4 >> 1), t);

#pragma unroll
        for (int nt = 0; nt < 4; nt++)
            mma_chain(D[nt], cw * 64 + (nt + 4) * 8, sbase, b_loff, ahi, alo);
#pragma unroll
        for (int nt = 0; nt < 4; nt++)
            gate_fold<MODE>(D[nt], c_st[nt + 4], sm, evn, myrow,
                            cw * 16 + (nt + 4) * 2 + (tid4 >> 1), t);

        __syncthreads();   // h complete; xp consumed

        if (WRITE_ALL || t == T_ - 1) {
            for (int i = tid; i < 32 * H_; i += 512) {
                int r = i >> 7, j2 = i & 127;
                float hi = __half2float(*(const __half*)(sm + OFF_H  + r * WROW + j2 * 2));
                float lo = __half2float(*(const __half*)(sm + OFF_HL + r * WROW + j2 * 2));
                g_h[((size_t)t * S_ + s0 + r) * H_ + j2] = hi + lo;
            }
        }
    }
}

// ---------------- tensor-core input projection (persistent, 512 thr) -------------
__global__ void __launch_bounds__(512, 1) proj_mma(
    const u32* __restrict__ w_h,
    const float* __restrict__ br)
{
    extern __shared__ __align__(16) char sm[];
    const u32 sbase = smem_u32(sm);

    const int tid = threadIdx.x, wid = tid >> 5, lane = tid & 31;
    const int grp = lane >> 2, tid4 = lane & 3;
    const int mt = wid >> 1, half = wid & 1;

    for (int i = tid; i < 512 * 64; i += 512) {
        int r = i >> 6, c = i & 63;
        *(u32*)(sm + OFF_W + r * WROW + c * 4) = w_h[i];
    }

    const int qa = lane >> 3;
    const int a_loff = ((lane & 7) + (qa & 1) * 8) * WROW + ((qa >> 1) * 8) * 2;
    const int b_loff = (lane & 7) * WROW + qa * 16;

    const int ntiles = (T_ * S_) / 128;   // 2048
    for (int rt = blockIdx.x; rt < ntiles; rt += gridDim.x) {
        __syncthreads();
        const float2* src = (const float2*)(g_h + (size_t)rt * 128 * H_);
        for (int i = tid; i < 128 * 64; i += 512) {
            int row = i >> 6, kp = i & 63;
            float2 v = src[i];
            __half hx = __float2half_rn(v.x), hy = __float2half_rn(v.y);
            u32 hip = ((u32)*(u16*)&hy << 16) | *(u16*)&hx;
            __half lx = __float2half_rn(v.x - __half2float(hx));
            __half ly = __float2half_rn(v.y - __half2float(hy));
            u32 lop = ((u32)*(u16*)&ly << 16) | *(u16*)&lx;
            *(u32*)(sm + OFF_AH + row * WROW + kp * 4) = hip;
            *(u32*)(sm + OFF_AL + row * WROW + kp * 4) = lop;
        }
        __syncthreads();

        u32 ahi[8][4], alo[8][4];
        const u32 abase_h = sbase + OFF_AH + mt * 16 * WROW + a_loff;
        const u32 abase_l = sbase + OFF_AL + mt * 16 * WROW + a_loff;
#pragma unroll
        for (int ks = 0; ks < 8; ks++) {
            LDSM4(ahi[ks], abase_h + ks * 32);
            LDSM4(alo[ks], abase_l + ks * 32);
        }

#pragma unroll 2
        for (int nt = half * 32; nt < half * 32 + 32; nt++) {
            const int n0 = nt * 8;
            u32 bb[8][2];
#pragma unroll
            for (int kc = 0; kc < 4; kc++) {
                u32 r[4];
                LDSM4(r, sbase + OFF_W + n0 * WROW + b_loff + kc * 64);
                bb[kc * 2][0] = r[0]; bb[kc * 2][1] = r[1];
                bb[kc * 2 + 1][0] = r[2]; bb[kc * 2 + 1][1] = r[3];
            }
            float2 bbv = *(const float2*)&br[n0 + tid4 * 2];
            float D[4] = {bbv.x, bbv.y, bbv.x, bbv.y};
#pragma unroll
            for (int ks = 0; ks < 8; ks++) mma_f16(D, ahi[ks], bb[ks][0], bb[ks][1]);
#pragma unroll
            for (int ks = 0; ks < 8; ks++) mma_f16(D, alo[ks], bb[ks][0], bb[ks][1]);

            size_t rowA = ((size_t)rt * 128 + mt * 16 + grp) * G4H;
            size_t rowB = rowA + 8 * G4H;
            *(float2*)&g_xp[rowA + n0 + tid4 * 2] = make_float2(D[0], D[1]);
            *(float2*)&g_xp[rowB + n0 + tid4 * 2] = make_float2(D[2], D[3]);
        }
    }
}

// ---------------- GCN -------------------------------------------------------------
__global__ void k_lin1(const float* __restrict__ w) {
    __shared__ float fr[8][H_];
    int r0 = blockIdx.x * 8, tid = threadIdx.x;   // 512 blocks, 128 thr
    for (int i = tid; i < 8 * H_; i += 128) {
        int r = i >> 7, k = i & 127;
        fr[r][k] = g_h[((size_t)(T_ - 1) * S_ + r0 + r) * H_ + k];
    }
    __syncthreads();
    const float* wr = w + tid * H_;
    float acc[8] = {0, 0, 0, 0, 0, 0, 0, 0};
#pragma unroll 4
    for (int k = 0; k < H_; k++) {
        float wk = wr[k];
#pragma unroll
        for (int r = 0; r < 8; r++) acc[r] = fmaf(fr[r][k], wk, acc[r]);
    }
#pragma unroll
    for (int r = 0; r < 8; r++) g_xl1[(r0 + r) * G1_ + tid] = acc[r];
}

__global__ void k_lin2(const float* __restrict__ w) {
    __shared__ float fr[8][G1_];
    int r0 = blockIdx.x * 8, tid = threadIdx.x;   // 512 blocks, 64 thr
    for (int i = tid; i < 8 * G1_; i += 64) {
        int r = i >> 7, k = i & 127;
        fr[r][k] = fmaxf(g_h1[(r0 + r) * G1_ + k], 0.0f);
    }
    __syncthreads();
    const float* wr = w + tid * G1_;
    float acc[8] = {0, 0, 0, 0, 0, 0, 0, 0};
#pragma unroll 4
    for (int k = 0; k < G1_; k++) {
        float wk = wr[k];
#pragma unroll
        for (int r = 0; r < 8; r++) acc[r] = fmaf(fr[r][k], wk, acc[r]);
    }
#pragma unroll
    for (int r = 0; r < 8; r++) g_xl2[(r0 + r) * G2_ + tid] = acc[r];
}

template <int Gd>
__global__ void k_agg_init(const float* __restrict__ bias) {
    const float* xl = (Gd == G1_) ? g_xl1 : g_xl2;
    float* outb     = (Gd == G1_) ? g_h1  : g_h2;
    int i = blockIdx.x * blockDim.x + threadIdx.x;
    if (i < S_ * Gd) {
        int g = i % Gd;
        int n = (i / Gd) & (N_ - 1);
        float d = g_dis[n];
        outb[i] = bias[g] + xl[i] * d * d;
    }
}

template <int Gd>
__global__ void k_agg_edge(const void* __restrict__ ei) {
    constexpr int G4 = Gd / 4;
    const float* xl = (Gd == G1_) ? g_xl1 : g_xl2;
    float* outb     = (Gd == G1_) ? g_h1  : g_h2;
    int i = blockIdx.x * blockDim.x + threadIdx.x;
    constexpr int per = B_ * G4;
    if (i >= E_ * per) return;
    int e = i / per;
    int r = i - e * per;
    int b = r / G4;
    int g4 = r - b * G4;
    int is64 = g_is64;
    int src = edge_at(ei, is64, e);
    int dst = edge_at(ei, is64, E_ + e);
    float norm = g_dis[src] * g_dis[dst];
    float4 v = *(const float4*)&xl[(b * N_ + src) * Gd + g4 * 4];
    float* o = &outb[(b * N_ + dst) * Gd + g4 * 4];
    atomicAdd(o + 0, v.x * norm);
    atomicAdd(o + 1, v.y * norm);
    atomicAdd(o + 2, v.z * norm);
    atomicAdd(o + 3, v.w * norm);
}

__global__ void k_final(const float* __restrict__ cls_w,
                        const float* __restrict__ cls_b,
                        float* __restrict__ out) {
    int b = blockIdx.x, tid = threadIdx.x;
    __shared__ float red[256];
    float a = 0.0f;
    for (int i = tid; i < N_ * G2_; i += 256) {
        int g = i & (G2_ - 1);
        a = fmaf(fmaxf(g_h2[b * (N_ * G2_) + i], 0.0f), cls_w[g], a);
    }
    red[tid] = a;
    __syncthreads();
    for (int s = 128; s > 0; s >>= 1) {
        if (tid < s) red[tid] += red[tid + s];
        __syncthreads();
    }
    if (tid == 0) out[b] = red[0] * (1.0f / N_) + cls_b[0];
}

// ---------------- launch -----------------------------------------------------------
extern "C" void kernel_launch(void* const* d_in, const int* in_sizes, int n_in,
                              void* d_out, int out_size) {
    const float* x      = (const float*)d_in[0];
    const void*  ei     = d_in[1];
    const float* w_ih0  = (const float*)d_in[2];
    const float* w_hh0  = (const float*)d_in[3];
    const float* b_ih0  = (const float*)d_in[4];
    const float* b_hh0  = (const float*)d_in[5];
    const float* w_ih1  = (const float*)d_in[6];
    const float* w_hh1  = (const float*)d_in[7];
    const float* b_ih1  = (const float*)d_in[8];
    const float* b_hh1  = (const float*)d_in[9];
    const float* w_ih2  = (const float*)d_in[10];
    const float* w_hh2  = (const float*)d_in[11];
    const float* b_ih2  = (const float*)d_in[12];
    const float* b_hh2  = (const float*)d_in[13];
    const float* gcn1_w = (const float*)d_in[14];
    const float* gcn1_b = (const float*)d_in[15];
    const float* gcn2_w = (const float*)d_in[16];
    const float* gcn2_b = (const float*)d_in[17];
    const float* cls_w  = (const float*)d_in[18];
    const float* cls_b  = (const float*)d_in[19];
    float* out = (float*)d_out;

    u32 *whh, *wih;
    float *br, *w0r;
    cudaGetSymbolAddress((void**)&whh, g_whh_h);
    cudaGetSymbolAddress((void**)&wih, g_wih_h);
    cudaGetSymbolAddress((void**)&br, g_br);
    cudaGetSymbolAddress((void**)&w0r, g_w0r);

    cudaFuncSetAttribute(rec_mma<0, 1>, cudaFuncAttributeMaxDynamicSharedMemorySize, REC_SM);
    cudaFuncSetAttribute(rec_mma<1, 1>, cudaFuncAttributeMaxDynamicSharedMemorySize, REC_SM);
    cudaFuncSetAttribute(rec_mma<1, 0>, cudaFuncAttributeMaxDynamicSharedMemorySize, REC_SM);
    cudaFuncSetAttribute(proj_mma, cudaFuncAttributeMaxDynamicSharedMemorySize, PROJ_SM);

    constexpr int WN = G4H * 64;
    const int RB = S_ / 32;   // 128 blocks

    // launches 1-5 (setup), 6 = rec_mma<0> so ncu (-s 5 -c 1) profiles it
    k_detect<<<1, 512>>>((const int*)ei);                       // 1
    k_prep_w<<<WN / 256, 256>>>(w_hh0, whh + 0 * WN);           // 2
    k_prep_b<<<2, 256>>>(b_ih0, b_hh0, br + 0 * G4H);           // 3
    k_prep_w0<<<2, 256>>>(w_ih0, w0r);                          // 4
    k_prep_w<<<WN / 256, 256>>>(w_hh1, whh + 1 * WN);           // 5
    rec_mma<0, 1><<<RB, 512, REC_SM>>>(x, whh + 0 * WN, w0r, br + 0 * G4H);  // 6

    k_prep_w<<<WN / 256, 256>>>(w_ih1, wih + 0 * WN);
    k_prep_b<<<2, 256>>>(b_ih1, b_hh1, br + 1 * G4H);
    proj_mma<<<148, 512, PROJ_SM>>>(wih + 0 * WN, br + 1 * G4H);
    rec_mma<1, 1><<<RB, 512, REC_SM>>>(nullptr, whh + 1 * WN, nullptr, nullptr);

    k_prep_w<<<WN / 256, 256>>>(w_hh2, whh + 2 * WN);
    k_prep_w<<<WN / 256, 256>>>(w_ih2, wih + 1 * WN);
    k_prep_b<<<2, 256>>>(b_ih2, b_hh2, br + 2 * G4H);
    proj_mma<<<148, 512, PROJ_SM>>>(wih + 1 * WN, br + 2 * G4H);
    rec_mma<1, 0><<<RB, 512, REC_SM>>>(nullptr, whh + 2 * WN, nullptr, nullptr);

    // GCN
    k_deg<<<(E_ + 255) / 256, 256>>>(ei);
    k_dis<<<2, 256>>>();

    k_lin1<<<S_ / 8, 128>>>(gcn1_w);
    k_agg_init<G1_><<<(S_ * G1_ + 255) / 256, 256>>>(gcn1_b);
    k_agg_edge<G1_><<<(E_ * B_ * (G1_ / 4) + 255) / 256, 256>>>(ei);

    k_lin2<<<S_ / 8, 64>>>(gcn2_w);
    k_agg_init<G2_><<<(S_ * G2_ + 255) / 256, 256>>>(gcn2_b);
    k_agg_edge<G2_><<<(E_ * B_ * (G2_ / 4) + 255) / 256, 256>>>(ei);

    k_final<<<B_, 256>>>(cls_w, cls_b, out);
}

// round 9
// speedup vs baseline: 4.9750x; 1.2007x over previous
#include <cuda_runtime.h>
#include <cuda_fp16.h>

#define DINLINE __device__ __forceinline__
typedef unsigned int u32;
typedef unsigned short u16;

constexpr int B_ = 8, T_ = 64, N_ = 512, H_ = 128, E_ = 8192;
constexpr int S_ = B_ * N_;       // 4096 sequences
constexpr int G1_ = 128, G2_ = 64;
constexpr int G4H = 4 * H_;       // 512 gate rows

// ---------------- SMEM layout (byte offsets) -----------------------------------
constexpr int WROW    = 272;                   // 136 fp16 per row (128 + 8 pad)
constexpr int OFF_W   = 0;                     // 512*272 = 139264
constexpr int OFF_H   = 139264;                // h plane (32 x 272), fp16
constexpr int HPLANE  = 32 * WROW;             // 8704
constexpr int OFF_XP  = OFF_H + HPLANE;        // 147968: xp staging (MODE 1)
constexpr int XPROW   = 2064;                  // 512 floats + 16B pad
constexpr int REC_SM  = OFF_XP + 32 * XPROW;   // 214016
// MODE 0 reuse of the XP region:
constexpr int OFF_SX  = OFF_XP;                // 64*32 fp32 = 8192
constexpr int OFF_W0S = OFF_SX + 8192;         // 512 fp32
constexpr int OFF_BRS = OFF_W0S + 2048;        // 512 fp32

constexpr int OFF_AH  = 139264;                // proj: A plane 128*272
constexpr int APLANE  = 128 * WROW;            // 34816
constexpr int PROJ_SM = OFF_AH + APLANE;       // 174080

// ---------------- device scratch (static globals; no allocation) ---------------
__device__ __half g_hh[(size_t)T_ * S_ * H_];    // [t*S+s][j]    64 MiB, fp16
__device__ float g_xp[(size_t)T_ * S_ * G4H];    // [t*S+s][4j+g] 512 MiB
__device__ u32   g_whh_h[3][G4H * 64];           // permuted fp16-pair W_hh
__device__ u32   g_wih_h[2][G4H * 64];           // permuted fp16-pair W_ih
__device__ float g_br[3][G4H];                   // b_ih+b_hh permuted (4j+g)
__device__ float g_w0r[G4H];                     // w_ih0 permuted
__device__ float g_xl1[S_ * G1_];
__device__ float g_h1[S_ * G1_];
__device__ float g_xl2[S_ * G2_];
__device__ float g_h2[S_ * G2_];
__device__ float g_deg[N_];
__device__ float g_dis[N_];
__device__ int   g_is64;

// ---------------- helpers -------------------------------------------------------
DINLINE float clamp14(float x) { return fminf(fmaxf(x, -14.0f), 14.0f); }

DINLINE u32 smem_u32(const void* p) {
    u32 a;
    asm("{ .reg .u64 t; cvta.to.shared.u64 t, %1; cvt.u32.u64 %0, t; }" : "=r"(a) : "l"(p));
    return a;
}

DINLINE void mma_f16(float* D, const u32* A, u32 b0, u32 b1) {
    asm("mma.sync.aligned.m16n8k16.row.col.f32.f16.f16.f32 "
        "{%0,%1,%2,%3},{%4,%5,%6,%7},{%8,%9},{%0,%1,%2,%3};"
        : "+f"(D[0]), "+f"(D[1]), "+f"(D[2]), "+f"(D[3])
        : "r"(A[0]), "r"(A[1]), "r"(A[2]), "r"(A[3]), "r"(b0), "r"(b1));
}

#define LDSM4(R, ADDR) \
    asm volatile("ldmatrix.sync.aligned.m8n8.x4.shared.b16 {%0,%1,%2,%3},[%4];" \
        : "=r"((R)[0]), "=r"((R)[1]), "=r"((R)[2]), "=r"((R)[3]) : "r"(ADDR))

DINLINE void cp_async16(u32 dst, const void* src) {
    asm volatile("cp.async.cg.shared.global [%0], [%1], 16;" :: "r"(dst), "l"(src) : "memory");
}
#define CP_COMMIT() asm volatile("cp.async.commit_group;" ::: "memory")
#define CP_WAIT0()  asm volatile("cp.async.wait_group 0;" ::: "memory")

DINLINE u32 packh(float a, float b) {
    __half2 h = __floats2half2_rn(a, b);
    return *(u32*)&h;
}

// ---------------- edge dtype detection + degree init ----------------------------
__global__ void k_detect(const int* __restrict__ ei32) {
    __shared__ int nz;
    int tid = threadIdx.x;
    if (tid == 0) nz = 0;
    if (tid < N_) g_deg[tid] = 1.0f;
    __syncthreads();
    int acc = 0;
    for (int i = 1 + 2 * tid; i < 2 * E_; i += 2 * blockDim.x) acc |= ei32[i];
    if (acc) atomicOr(&nz, 1);
    __syncthreads();
    if (tid == 0) g_is64 = (nz == 0) ? 1 : 0;
}

DINLINE int edge_at(const void* p, int is64, int idx) {
    return is64 ? (int)((const long long*)p)[idx] : ((const int*)p)[idx];
}

__global__ void k_deg(const void* __restrict__ ei) {
    int e = blockIdx.x * blockDim.x + threadIdx.x;
    if (e < E_) atomicAdd(&g_deg[edge_at(ei, g_is64, E_ + e)], 1.0f);
}

__global__ void k_dis() {
    int n = blockIdx.x * blockDim.x + threadIdx.x;
    if (n < N_) g_dis[n] = rsqrtf(g_deg[n]);
}

// ---------------- weight prep: permute rows (4j+g), fp16-pair pack --------------
__global__ void k_prep_w(const float* __restrict__ w, u32* __restrict__ outw) {
    int i = blockIdx.x * blockDim.x + threadIdx.x;   // 512*64
    int colp = i >> 6, kp = i & 63;
    int j = colp >> 2, g = colp & 3;
    const float* wr = w + (g * H_ + j) * H_ + 2 * kp;
    outw[i] = packh(wr[0], wr[1]);
}

__global__ void k_prep_b(const float* __restrict__ bi, const float* __restrict__ bh,
                         float* __restrict__ outb) {
    int colp = blockIdx.x * blockDim.x + threadIdx.x;
    if (colp < G4H) {
        int j = colp >> 2, g = colp & 3;
        outb[colp] = bi[g * H_ + j] + bh[g * H_ + j];
    }
}

__global__ void k_prep_w0(const float* __restrict__ w, float* __restrict__ outw) {
    int colp = blockIdx.x * blockDim.x + threadIdx.x;
    if (colp < G4H) {
        int j = colp >> 2, g = colp & 3;
        outw[colp] = w[g * H_ + j];
    }
}

// ---------------- MMA chain for one 16x8 n-tile (single-plane h) -----------------
DINLINE void mma_chain(float* D, int n0, u32 sbase, int b_loff,
                       const u32 (*ahi)[4]) {
    u32 bb[8][2];
#pragma unroll
    for (int kc = 0; kc < 4; kc++) {
        u32 r[4];
        LDSM4(r, sbase + OFF_W + n0 * WROW + b_loff + kc * 64);
        bb[kc * 2][0] = r[0]; bb[kc * 2][1] = r[1];
        bb[kc * 2 + 1][0] = r[2]; bb[kc * 2 + 1][1] = r[3];
    }
    D[0] = D[1] = D[2] = D[3] = 0.0f;
#pragma unroll
    for (int ks = 0; ks < 8; ks++) mma_f16(D, ahi[ks], bb[ks][0], bb[ks][1]);
}

// ---------------- gate fold: shuffle, input add, activations, h write ------------
template <int MODE>
DINLINE void gate_fold(float* D, float& c_ref, char* sm, bool evn,
                       int myrow, int j, int t) {
    float sv0 = evn ? D[2] : D[0];
    float rr0 = __shfl_xor_sync(0xffffffffu, sv0, 1);
    float sv1 = evn ? D[3] : D[1];
    float rr1 = __shfl_xor_sync(0xffffffffu, sv1, 1);
    float pi = evn ? D[0] : rr0;
    float pf = evn ? D[1] : rr1;
    float pg = evn ? rr0 : D[2];
    float po = evn ? rr1 : D[3];

    if (MODE == 1) {
        float4 xq = *(const float4*)(sm + OFF_XP + myrow * XPROW + j * 16);
        pi += xq.x; pf += xq.y; pg += xq.z; po += xq.w;
    } else {
        float xv = ((const float*)(sm + OFF_SX))[t * 32 + myrow];
        float4 w4 = ((const float4*)(sm + OFF_W0S))[j];
        float4 b4 = ((const float4*)(sm + OFF_BRS))[j];
        pi += xv * w4.x + b4.x;
        pf += xv * w4.y + b4.y;
        pg += xv * w4.z + b4.z;
        po += xv * w4.w + b4.w;
    }
    pi = clamp14(pi); pf = clamp14(pf); pg = clamp14(pg); po = clamp14(po);

    float ea = __expf(-pf);
    float eb = __expf(-pi);
    float G  = __expf(2.0f * pg);
    float t1 = (1.0f + eb) * (G + 1.0f);
    float cn = __fdividef(c_ref * t1 + (G - 1.0f) * (1.0f + ea),
                          (1.0f + ea) * t1);
    c_ref = cn;
    float ed = __expf(-po);
    float Hc = __expf(2.0f * clamp14(cn));
    float hv = __fdividef(Hc - 1.0f, (1.0f + ed) * (Hc + 1.0f));

    *(__half*)(sm + OFF_H + myrow * WROW + j * 2) = __float2half_rn(hv);
}

// ---------------- tensor-core LSTM recurrence ------------------------------------
// 512 threads, 16 warps: mt = wid&1 (row half), cw = wid>>1 (64 gate cols).
template <int MODE, int WRITE_ALL>
__global__ void __launch_bounds__(512, 1) rec_mma(
    const float* __restrict__ x,               // MODE 0
    const u32* __restrict__ w_h,               // [512][64] fp16 pairs
    const float* __restrict__ w0r,             // MODE 0
    const float* __restrict__ br0)             // MODE 0
{
    extern __shared__ __align__(16) char sm[];
    const u32 sbase = smem_u32(sm);

    const int tid = threadIdx.x, wid = tid >> 5, lane = tid & 31;
    const int grp = lane >> 2, tid4 = lane & 3;
    const bool evn = (tid4 & 1) == 0;
    const int mt = wid & 1, cw = wid >> 1;
    const int s0 = blockIdx.x * 32;

    for (int i = tid; i < 512 * 64; i += 512) {
        int r = i >> 6, c = i & 63;
        *(u32*)(sm + OFF_W + r * WROW + c * 4) = w_h[i];
    }
    for (int i = tid; i < HPLANE / 4; i += 512)
        ((u32*)(sm + OFF_H))[i] = 0;
    if (MODE == 0) {
        float* sx = (float*)(sm + OFF_SX);
        for (int i = tid; i < 64 * 32; i += 512) {
            int t = i >> 5, m = i & 31;
            int s = s0 + m;
            sx[i] = x[(s >> 9) * (T_ * N_) + t * N_ + (s & (N_ - 1))];
        }
        if (tid < 512) {
            ((float*)(sm + OFF_W0S))[tid] = w0r[tid];
            ((float*)(sm + OFF_BRS))[tid] = br0[tid];
        }
    }
    __syncthreads();

    const int qa = lane >> 3;
    const int a_loff = ((lane & 7) + (qa & 1) * 8) * WROW + ((qa >> 1) * 8) * 2;
    const int b_loff = (lane & 7) * WROW + qa * 16;
    const u32 a_hi = sbase + OFF_H + mt * 16 * WROW + a_loff;
    const int myrow = mt * 16 + (evn ? grp : grp + 8);

    float c_st[8];
#pragma unroll
    for (int q = 0; q < 8; q++) c_st[q] = 0.0f;

    for (int t = 0; t < T_; t++) {
        if (MODE == 1) {
#pragma unroll
            for (int q = 0; q < 8; q++) {
                int chunk = q * 512 + tid;
                int r = chunk >> 7, c16 = chunk & 127;
                cp_async16(sbase + OFF_XP + r * XPROW + c16 * 16,
                           g_xp + ((size_t)t * S_ + s0 + r) * G4H + c16 * 4);
            }
            CP_COMMIT();
        }

        u32 ahi[8][4];
#pragma unroll
        for (int ks = 0; ks < 8; ks++) LDSM4(ahi[ks], a_hi + ks * 32);

        float D[4][4];
#pragma unroll
        for (int nt = 0; nt < 4; nt++)
            mma_chain(D[nt], cw * 64 + nt * 8, sbase, b_loff, ahi);

        if (MODE == 1) CP_WAIT0();
        __syncthreads();   // all A-reads done everywhere; xp visible

#pragma unroll
        for (int nt = 0; nt < 4; nt++)
            gate_fold<MODE>(D[nt], c_st[nt], sm, evn, myrow,
                            cw * 16 + nt * 2 + (tid4 >> 1), t);

#pragma unroll
        for (int nt = 0; nt < 4; nt++)
            mma_chain(D[nt], cw * 64 + (nt + 4) * 8, sbase, b_loff, ahi);
#pragma unroll
        for (int nt = 0; nt < 4; nt++)
            gate_fold<MODE>(D[nt], c_st[nt + 4], sm, evn, myrow,
                            cw * 16 + (nt + 4) * 2 + (tid4 >> 1), t);

        __syncthreads();   // h complete; xp consumed

        if (WRITE_ALL || t == T_ - 1) {
            // copy fp16 h plane to global (u32 = 2 cols)
            for (int i = tid; i < 32 * 64; i += 512) {
                int r = i >> 6, jp = i & 63;
                u32 v = *(const u32*)(sm + OFF_H + r * WROW + jp * 4);
                *(u32*)&g_hh[((size_t)t * S_ + s0 + r) * H_ + jp * 2] = v;
            }
        }
    }
}

// ---------------- tensor-core input projection (persistent, 512 thr) -------------
__global__ void __launch_bounds__(512, 1) proj_mma(
    const u32* __restrict__ w_h,
    const float* __restrict__ br)
{
    extern __shared__ __align__(16) char sm[];
    const u32 sbase = smem_u32(sm);

    const int tid = threadIdx.x, wid = tid >> 5, lane = tid & 31;
    const int grp = lane >> 2, tid4 = lane & 3;
    const int mt = wid >> 1, half = wid & 1;

    for (int i = tid; i < 512 * 64; i += 512) {
        int r = i >> 6, c = i & 63;
        *(u32*)(sm + OFF_W + r * WROW + c * 4) = w_h[i];
    }

    const int qa = lane >> 3;
    const int a_loff = ((lane & 7) + (qa & 1) * 8) * WROW + ((qa >> 1) * 8) * 2;
    const int b_loff = (lane & 7) * WROW + qa * 16;

    const int ntiles = (T_ * S_) / 128;   // 2048
    for (int rt = blockIdx.x; rt < ntiles; rt += gridDim.x) {
        __syncthreads();
        // stage h tile (fp16, raw copy)
        const u32* src = (const u32*)(g_hh + (size_t)rt * 128 * H_);
        for (int i = tid; i < 128 * 64; i += 512) {
            int row = i >> 6, kp = i & 63;
            *(u32*)(sm + OFF_AH + row * WROW + kp * 4) = src[i];
        }
        __syncthreads();

        u32 ahi[8][4];
        const u32 abase_h = sbase + OFF_AH + mt * 16 * WROW + a_loff;
#pragma unroll
        for (int ks = 0; ks < 8; ks++) LDSM4(ahi[ks], abase_h + ks * 32);

#pragma unroll 2
        for (int nt = half * 32; nt < half * 32 + 32; nt++) {
            const int n0 = nt * 8;
            u32 bb[8][2];
#pragma unroll
            for (int kc = 0; kc < 4; kc++) {
                u32 r[4];
                LDSM4(r, sbase + OFF_W + n0 * WROW + b_loff + kc * 64);
                bb[kc * 2][0] = r[0]; bb[kc * 2][1] = r[1];
                bb[kc * 2 + 1][0] = r[2]; bb[kc * 2 + 1][1] = r[3];
            }
            float2 bbv = *(const float2*)&br[n0 + tid4 * 2];
            float D[4] = {bbv.x, bbv.y, bbv.x, bbv.y};
#pragma unroll
            for (int ks = 0; ks < 8; ks++) mma_f16(D, ahi[ks], bb[ks][0], bb[ks][1]);

            size_t rowA = ((size_t)rt * 128 + mt * 16 + grp) * G4H;
            size_t rowB = rowA + 8 * G4H;
            *(float2*)&g_xp[rowA + n0 + tid4 * 2] = make_float2(D[0], D[1]);
            *(float2*)&g_xp[rowB + n0 + tid4 * 2] = make_float2(D[2], D[3]);
        }
    }
}

// ---------------- GCN -------------------------------------------------------------
__global__ void k_lin1(const float* __restrict__ w) {
    __shared__ float fr[8][H_];
    int r0 = blockIdx.x * 8, tid = threadIdx.x;   // 512 blocks, 128 thr
    for (int i = tid; i < 8 * H_; i += 128) {
        int r = i >> 7, k = i & 127;
        fr[r][k] = __half2float(g_hh[((size_t)(T_ - 1) * S_ + r0 + r) * H_ + k]);
    }
    __syncthreads();
    const float* wr = w + tid * H_;
    float acc[8] = {0, 0, 0, 0, 0, 0, 0, 0};
#pragma unroll 4
    for (int k = 0; k < H_; k++) {
        float wk = wr[k];
#pragma unroll
        for (int r = 0; r < 8; r++) acc[r] = fmaf(fr[r][k], wk, acc[r]);
    }
#pragma unroll
    for (int r = 0; r < 8; r++) g_xl1[(r0 + r) * G1_ + tid] = acc[r];
}

__global__ void k_lin2(const float* __restrict__ w) {
    __shared__ float fr[8][G1_];
    int r0 = blockIdx.x * 8, tid = threadIdx.x;   // 512 blocks, 64 thr
    for (int i = tid; i < 8 * G1_; i += 64) {
        int r = i >> 7, k = i & 127;
        fr[r][k] = fmaxf(g_h1[(r0 + r) * G1_ + k], 0.0f);
    }
    __syncthreads();
    const float* wr = w + tid * G1_;
    float acc[8] = {0, 0, 0, 0, 0, 0, 0, 0};
#pragma unroll 4
    for (int k = 0; k < G1_; k++) {
        float wk = wr[k];
#pragma unroll
        for (int r = 0; r < 8; r++) acc[r] = fmaf(fr[r][k], wk, acc[r]);
    }
#pragma unroll
    for (int r = 0; r < 8; r++) g_xl2[(r0 + r) * G2_ + tid] = acc[r];
}

template <int Gd>
__global__ void k_agg_init(const float* __restrict__ bias) {
    const float* xl = (Gd == G1_) ? g_xl1 : g_xl2;
    float* outb     = (Gd == G1_) ? g_h1  : g_h2;
    int i = blockIdx.x * blockDim.x + threadIdx.x;
    if (i < S_ * Gd) {
        int g = i % Gd;
        int n = (i / Gd) & (N_ - 1);
        float d = g_dis[n];
        outb[i] = bias[g] + xl[i] * d * d;
    }
}

template <int Gd>
__global__ void k_agg_edge(const void* __restrict__ ei) {
    constexpr int G4 = Gd / 4;
    const float* xl = (Gd == G1_) ? g_xl1 : g_xl2;
    float* outb     = (Gd == G1_) ? g_h1  : g_h2;
    int i = blockIdx.x * blockDim.x + threadIdx.x;
    constexpr int per = B_ * G4;
    if (i >= E_ * per) return;
    int e = i / per;
    int r = i - e * per;
    int b = r / G4;
    int g4 = r - b * G4;
    int is64 = g_is64;
    int src = edge_at(ei, is64, e);
    int dst = edge_at(ei, is64, E_ + e);
    float norm = g_dis[src] * g_dis[dst];
    float4 v = *(const float4*)&xl[(b * N_ + src) * Gd + g4 * 4];
    float* o = &outb[(b * N_ + dst) * Gd + g4 * 4];
    atomicAdd(o + 0, v.x * norm);
    atomicAdd(o + 1, v.y * norm);
    atomicAdd(o + 2, v.z * norm);
    atomicAdd(o + 3, v.w * norm);
}

__global__ void k_final(const float* __restrict__ cls_w,
                        const float* __restrict__ cls_b,
                        float* __restrict__ out) {
    int b = blockIdx.x, tid = threadIdx.x;
    __shared__ float red[256];
    float a = 0.0f;
    for (int i = tid; i < N_ * G2_; i += 256) {
        int g = i & (G2_ - 1);
        a = fmaf(fmaxf(g_h2[b * (N_ * G2_) + i], 0.0f), cls_w[g], a);
    }
    red[tid] = a;
    __syncthreads();
    for (int s = 128; s > 0; s >>= 1) {
        if (tid < s) red[tid] += red[tid + s];
        __syncthreads();
    }
    if (tid == 0) out[b] = red[0] * (1.0f / N_) + cls_b[0];
}

// ---------------- launch -----------------------------------------------------------
extern "C" void kernel_launch(void* const* d_in, const int* in_sizes, int n_in,
                              void* d_out, int out_size) {
    const float* x      = (const float*)d_in[0];
    const void*  ei     = d_in[1];
    const float* w_ih0  = (const float*)d_in[2];
    const float* w_hh0  = (const float*)d_in[3];
    const float* b_ih0  = (const float*)d_in[4];
    const float* b_hh0  = (const float*)d_in[5];
    const float* w_ih1  = (const float*)d_in[6];
    const float* w_hh1  = (const float*)d_in[7];
    const float* b_ih1  = (const float*)d_in[8];
    const float* b_hh1  = (const float*)d_in[9];
    const float* w_ih2  = (const float*)d_in[10];
    const float* w_hh2  = (const float*)d_in[11];
    const float* b_ih2  = (const float*)d_in[12];
    const float* b_hh2  = (const float*)d_in[13];
    const float* gcn1_w = (const float*)d_in[14];
    const float* gcn1_b = (const float*)d_in[15];
    const float* gcn2_w = (const float*)d_in[16];
    const float* gcn2_b = (const float*)d_in[17];
    const float* cls_w  = (const float*)d_in[18];
    const float* cls_b  = (const float*)d_in[19];
    float* out = (float*)d_out;

    u32 *whh, *wih;
    float *br, *w0r;
    cudaGetSymbolAddress((void**)&whh, g_whh_h);
    cudaGetSymbolAddress((void**)&wih, g_wih_h);
    cudaGetSymbolAddress((void**)&br, g_br);
    cudaGetSymbolAddress((void**)&w0r, g_w0r);

    cudaFuncSetAttribute(rec_mma<0, 1>, cudaFuncAttributeMaxDynamicSharedMemorySize, REC_SM);
    cudaFuncSetAttribute(rec_mma<1, 1>, cudaFuncAttributeMaxDynamicSharedMemorySize, REC_SM);
    cudaFuncSetAttribute(rec_mma<1, 0>, cudaFuncAttributeMaxDynamicSharedMemorySize, REC_SM);
    cudaFuncSetAttribute(proj_mma, cudaFuncAttributeMaxDynamicSharedMemorySize, PROJ_SM);

    constexpr int WN = G4H * 64;
    const int RB = S_ / 32;   // 128 blocks

    // launches 1-5 (setup), 6 = rec_mma<0> so ncu (-s 5 -c 1) profiles it
    k_detect<<<1, 512>>>((const int*)ei);                       // 1
    k_prep_w<<<WN / 256, 256>>>(w_hh0, whh + 0 * WN);           // 2
    k_prep_b<<<2, 256>>>(b_ih0, b_hh0, br + 0 * G4H);           // 3
    k_prep_w0<<<2, 256>>>(w_ih0, w0r);                          // 4
    k_prep_w<<<WN / 256, 256>>>(w_hh1, whh + 1 * WN);           // 5
    rec_mma<0, 1><<<RB, 512, REC_SM>>>(x, whh + 0 * WN, w0r, br + 0 * G4H);  // 6

    k_prep_w<<<WN / 256, 256>>>(w_ih1, wih + 0 * WN);
    k_prep_b<<<2, 256>>>(b_ih1, b_hh1, br + 1 * G4H);
    proj_mma<<<148, 512, PROJ_SM>>>(wih + 0 * WN, br + 1 * G4H);
    rec_mma<1, 1><<<RB, 512, REC_SM>>>(nullptr, whh + 1 * WN, nullptr, nullptr);

    k_prep_w<<<WN / 256, 256>>>(w_hh2, whh + 2 * WN);
    k_prep_w<<<WN / 256, 256>>>(w_ih2, wih + 1 * WN);
    k_prep_b<<<2, 256>>>(b_ih2, b_hh2, br + 2 * G4H);
    proj_mma<<<148, 512, PROJ_SM>>>(wih + 1 * WN, br + 2 * G4H);
    rec_mma<1, 0><<<RB, 512, REC_SM>>>(nullptr, whh + 2 * WN, nullptr, nullptr);

    // GCN
    k_deg<<<(E_ + 255) / 256, 256>>>(ei);
    k_dis<<<2, 256>>>();

    k_lin1<<<S_ / 8, 128>>>(gcn1_w);
    k_agg_init<G1_><<<(S_ * G1_ + 255) / 256, 256>>>(gcn1_b);
    k_agg_edge<G1_><<<(E_ * B_ * (G1_ / 4) + 255) / 256, 256>>>(ei);

    k_lin2<<<S_ / 8, 64>>>(gcn2_w);
    k_agg_init<G2_><<<(S_ * G2_ + 255) / 256, 256>>>(gcn2_b);
    k_agg_edge<G2_><<<(E_ * B_ * (G2_ / 4) + 255) / 256, 256>>>(ei);

    k_final<<<B_, 256>>>(cls_w, cls_b, out);
}

// round 10
// speedup vs baseline: 5.9874x; 1.2035x over previous
#include <cuda_runtime.h>
#include <cuda_fp16.h>

#define DINLINE __device__ __forceinline__
typedef unsigned int u32;
typedef unsigned short u16;

constexpr int B_ = 8, T_ = 64, N_ = 512, H_ = 128, E_ = 8192;
constexpr int S_ = B_ * N_;       // 4096 sequences
constexpr int G1_ = 128, G2_ = 64;
constexpr int G4H = 4 * H_;       // 512 gate rows

// ---------------- SMEM layout (byte offsets) -----------------------------------
constexpr int WROW    = 272;                   // 136 fp16 per row (128 + 8 pad)
constexpr int OFF_W   = 0;                     // 512*272 = 139264
constexpr int OFF_H   = 139264;                // h planes (2 x 32 x 272), fp16
constexpr int HPLANE  = 32 * WROW;             // 8704
constexpr int OFF_SX  = OFF_H + 2 * HPLANE;    // 156672 (MODE 0 only)
constexpr int OFF_W0S = OFF_SX + 8192;
constexpr int OFF_BRS = OFF_W0S + 2048;
constexpr int REC_SM  = OFF_BRS + 2048;        // 168960

constexpr int OFF_AH  = 139264;                // proj: A plane 128*272
constexpr int APLANE  = 128 * WROW;            // 34816
constexpr int PROJ_SM = OFF_AH + APLANE;       // 174080

// ---------------- device scratch (static globals; no allocation) ---------------
__device__ __half g_hh [(size_t)T_ * S_ * H_];   // [t*S+s][j]    64 MiB
__device__ __half g_xph[(size_t)T_ * S_ * G4H];  // [t*S+s][4j+g] 256 MiB
__device__ u32   g_whh_h[3][G4H * 64];           // permuted fp16-pair W_hh
__device__ u32   g_wih_h[2][G4H * 64];           // permuted fp16-pair W_ih
__device__ float g_br[3][G4H];                   // b_ih+b_hh permuted (4j+g)
__device__ float g_w0r[G4H];                     // w_ih0 permuted
__device__ float g_xl1[S_ * G1_];
__device__ float g_h1[S_ * G1_];
__device__ float g_xl2[S_ * G2_];
__device__ float g_h2[S_ * G2_];
__device__ float g_dis[N_];
__device__ int   g_is64;

// ---------------- helpers -------------------------------------------------------
DINLINE float tanhfast(float x) {
    float y;
    asm("tanh.approx.f32 %0, %1;" : "=f"(y) : "f"(x));
    return y;
}

DINLINE u32 smem_u32(const void* p) {
    u32 a;
    asm("{ .reg .u64 t; cvta.to.shared.u64 t, %1; cvt.u32.u64 %0, t; }" : "=r"(a) : "l"(p));
    return a;
}

DINLINE void mma_f16(float* D, const u32* A, u32 b0, u32 b1) {
    asm("mma.sync.aligned.m16n8k16.row.col.f32.f16.f16.f32 "
        "{%0,%1,%2,%3},{%4,%5,%6,%7},{%8,%9},{%0,%1,%2,%3};"
        : "+f"(D[0]), "+f"(D[1]), "+f"(D[2]), "+f"(D[3])
        : "r"(A[0]), "r"(A[1]), "r"(A[2]), "r"(A[3]), "r"(b0), "r"(b1));
}

#define LDSM4(R, ADDR) \
    asm volatile("ldmatrix.sync.aligned.m8n8.x4.shared.b16 {%0,%1,%2,%3},[%4];" \
        : "=r"((R)[0]), "=r"((R)[1]), "=r"((R)[2]), "=r"((R)[3]) : "r"(ADDR))

DINLINE u32 packh(float a, float b) {
    __half2 h = __floats2half2_rn(a, b);
    return *(u32*)&h;
}

DINLINE int edge_at(const void* p, int is64, int idx) {
    return is64 ? (int)((const long long*)p)[idx] : ((const int*)p)[idx];
}

// ---------------- fused edge prep: dtype detect + degree + rsqrt ----------------
__global__ void k_edge_prep(const void* __restrict__ ei) {
    __shared__ float sdeg[N_];
    __shared__ int nz;
    const int tid = threadIdx.x;   // 512 threads
    if (tid == 0) nz = 0;
    sdeg[tid] = 1.0f;              // self-loop
    __syncthreads();
    const int* ei32 = (const int*)ei;
    int acc = 0;
    for (int i = 1 + 2 * tid; i < 2 * E_; i += 1024) acc |= ei32[i];
    if (acc) atomicOr(&nz, 1);
    __syncthreads();
    int is64 = (nz == 0) ? 1 : 0;
    if (tid == 0) g_is64 = is64;
    for (int e = tid; e < E_; e += 512)
        atomicAdd(&sdeg[edge_at(ei, is64, E_ + e)], 1.0f);
    __syncthreads();
    g_dis[tid] = rsqrtf(sdeg[tid]);
}

// ---------------- weight prep: permute rows (4j+g), fp16-pair pack --------------
__global__ void k_prep_w(const float* __restrict__ w, u32* __restrict__ outw) {
    int i = blockIdx.x * blockDim.x + threadIdx.x;   // 512*64
    int colp = i >> 6, kp = i & 63;
    int j = colp >> 2, g = colp & 3;
    const float* wr = w + (g * H_ + j) * H_ + 2 * kp;
    outw[i] = packh(wr[0], wr[1]);
}

__global__ void k_prep_b(const float* __restrict__ bi, const float* __restrict__ bh,
                         float* __restrict__ outb) {
    int colp = blockIdx.x * blockDim.x + threadIdx.x;
    if (colp < G4H) {
        int j = colp >> 2, g = colp & 3;
        outb[colp] = bi[g * H_ + j] + bh[g * H_ + j];
    }
}

__global__ void k_prep_bw0(const float* __restrict__ bi, const float* __restrict__ bh,
                           const float* __restrict__ w) {
    int colp = blockIdx.x * blockDim.x + threadIdx.x;
    if (colp < G4H) {
        int j = colp >> 2, g = colp & 3;
        g_br[0][colp] = bi[g * H_ + j] + bh[g * H_ + j];
        g_w0r[colp]   = w[g * H_ + j];
    }
}

// ---------------- MMA chain for one 16x8 n-tile ----------------------------------
DINLINE void mma_chain(float* D, int n0, u32 sbase, int b_loff, const u32 (*ahi)[4]) {
    u32 bb[8][2];
#pragma unroll
    for (int kc = 0; kc < 4; kc++) {
        u32 r[4];
        LDSM4(r, sbase + OFF_W + n0 * WROW + b_loff + kc * 64);
        bb[kc * 2][0] = r[0]; bb[kc * 2][1] = r[1];
        bb[kc * 2 + 1][0] = r[2]; bb[kc * 2 + 1][1] = r[3];
    }
    D[0] = D[1] = D[2] = D[3] = 0.0f;
#pragma unroll
    for (int ks = 0; ks < 8; ks++) mma_f16(D, ahi[ks], bb[ks][0], bb[ks][1]);
}

// ---------------- gate fold: shuffle, input add, activations, h write ------------
template <int MODE>
DINLINE void gate_fold(float* D, float& c_ref, char* sm, bool evn,
                       int myrow, int j, int t, int hw_off, uint2 xq) {
    float sv0 = evn ? D[2] : D[0];
    float rr0 = __shfl_xor_sync(0xffffffffu, sv0, 1);
    float sv1 = evn ? D[3] : D[1];
    float rr1 = __shfl_xor_sync(0xffffffffu, sv1, 1);
    float pi = evn ? D[0] : rr0;
    float pf = evn ? D[1] : rr1;
    float pg = evn ? rr0 : D[2];
    float po = evn ? rr1 : D[3];

    if (MODE == 1) {
        float2 fa = __half22float2(*(__half2*)&xq.x);
        float2 fb = __half22float2(*(__half2*)&xq.y);
        pi += fa.x; pf += fa.y; pg += fb.x; po += fb.y;
    } else {
        float xv = ((const float*)(sm + OFF_SX))[t * 32 + myrow];
        float4 w4 = ((const float4*)(sm + OFF_W0S))[j];
        float4 b4 = ((const float4*)(sm + OFF_BRS))[j];
        pi += xv * w4.x + b4.x;
        pf += xv * w4.y + b4.y;
        pg += xv * w4.z + b4.z;
        po += xv * w4.w + b4.w;
    }

    float si = fmaf(tanhfast(0.5f * pi), 0.5f, 0.5f);
    float sf = fmaf(tanhfast(0.5f * pf), 0.5f, 0.5f);
    float so = fmaf(tanhfast(0.5f * po), 0.5f, 0.5f);
    float cn = sf * c_ref + si * tanhfast(pg);
    c_ref = cn;
    float hv = so * tanhfast(cn);

    *(__half*)(sm + hw_off + myrow * WROW + j * 2) = __float2half_rn(hv);
}

// ---------------- tensor-core LSTM recurrence ------------------------------------
// 512 threads, 16 warps: mt = wid&1 (row half), cw = wid>>1 (64 gate cols).
// h double-buffered fp16 planes; ONE barrier per step; xp prefetched to regs.
template <int MODE, int WRITE_ALL>
__global__ void __launch_bounds__(512, 1) rec_mma(
    const float* __restrict__ x,               // MODE 0
    const u32* __restrict__ w_h,               // [512][64] fp16 pairs
    const float* __restrict__ w0r,             // MODE 0
    const float* __restrict__ br0)             // MODE 0
{
    extern __shared__ __align__(16) char sm[];
    const u32 sbase = smem_u32(sm);

    const int tid = threadIdx.x, wid = tid >> 5, lane = tid & 31;
    const int grp = lane >> 2, tid4 = lane & 3;
    const bool evn = (tid4 & 1) == 0;
    const int mt = wid & 1, cw = wid >> 1;
    const int s0 = blockIdx.x * 32;

    for (int i = tid; i < 512 * 64; i += 512) {
        int r = i >> 6, c = i & 63;
        *(u32*)(sm + OFF_W + r * WROW + c * 4) = w_h[i];
    }
    for (int i = tid; i < HPLANE / 4; i += 512)       // zero plane 0
        ((u32*)(sm + OFF_H))[i] = 0;
    if (MODE == 0) {
        float* sx = (float*)(sm + OFF_SX);
        for (int i = tid; i < 64 * 32; i += 512) {
            int t = i >> 5, m = i & 31;
            int s = s0 + m;
            sx[i] = x[(s >> 9) * (T_ * N_) + t * N_ + (s & (N_ - 1))];
        }
        if (tid < 512) {
            ((float*)(sm + OFF_W0S))[tid] = w0r[tid];
            ((float*)(sm + OFF_BRS))[tid] = br0[tid];
        }
    }
    __syncthreads();

    const int qa = lane >> 3;
    const int a_loff = ((lane & 7) + (qa & 1) * 8) * WROW + ((qa >> 1) * 8) * 2;
    const int b_loff = (lane & 7) * WROW + qa * 16;
    const int myrow = mt * 16 + (evn ? grp : grp + 8);

    float c_st[8];
#pragma unroll
    for (int q = 0; q < 8; q++) c_st[q] = 0.0f;

    for (int t = 0; t < T_; t++) {
        const int rb = t & 1, wb = rb ^ 1;
        const int hw_off = OFF_H + wb * HPLANE;

        // prefetch xp for this step (self-consumed; no barrier needed)
        uint2 xq[8];
        if (MODE == 1) {
            const __half* xpb = g_xph + ((size_t)t * S_ + s0 + myrow) * G4H
                                + cw * 64 + (tid4 >> 1) * 4;
#pragma unroll
            for (int nt = 0; nt < 8; nt++)
                xq[nt] = *(const uint2*)(xpb + nt * 8);
        }

        // A fragments from read plane
        u32 ahi[8][4];
        const u32 a_hi = sbase + OFF_H + rb * HPLANE + mt * 16 * WROW + a_loff;
#pragma unroll
        for (int ks = 0; ks < 8; ks++) LDSM4(ahi[ks], a_hi + ks * 32);

        float D[4][4];
#pragma unroll
        for (int nt = 0; nt < 4; nt++)
            mma_chain(D[nt], cw * 64 + nt * 8, sbase, b_loff, ahi);
#pragma unroll
        for (int nt = 0; nt < 4; nt++)
            gate_fold<MODE>(D[nt], c_st[nt], sm, evn, myrow,
                            cw * 16 + nt * 2 + (tid4 >> 1), t, hw_off, xq[nt]);

#pragma unroll
        for (int nt = 0; nt < 4; nt++)
            mma_chain(D[nt], cw * 64 + (nt + 4) * 8, sbase, b_loff, ahi);
#pragma unroll
        for (int nt = 0; nt < 4; nt++)
            gate_fold<MODE>(D[nt], c_st[nt + 4], sm, evn, myrow,
                            cw * 16 + (nt + 4) * 2 + (tid4 >> 1), t, hw_off, xq[nt + 4]);

        __syncthreads();   // h(wb) complete; A-reads of rb done

        if (WRITE_ALL || t == T_ - 1) {
            for (int i = tid; i < 32 * 64; i += 512) {
                int r = i >> 6, jp = i & 63;
                u32 v = *(const u32*)(sm + hw_off + r * WROW + jp * 4);
                *(u32*)&g_hh[((size_t)t * S_ + s0 + r) * H_ + jp * 2] = v;
            }
        }
    }
}

// ---------------- tensor-core input projection (persistent, 512 thr) -------------
__global__ void __launch_bounds__(512, 1) proj_mma(
    const u32* __restrict__ w_h,
    const float* __restrict__ br)
{
    extern __shared__ __align__(16) char sm[];
    const u32 sbase = smem_u32(sm);

    const int tid = threadIdx.x, wid = tid >> 5, lane = tid & 31;
    const int grp = lane >> 2, tid4 = lane & 3;
    const int mt = wid >> 1, half = wid & 1;

    for (int i = tid; i < 512 * 64; i += 512) {
        int r = i >> 6, c = i & 63;
        *(u32*)(sm + OFF_W + r * WROW + c * 4) = w_h[i];
    }

    const int qa = lane >> 3;
    const int a_loff = ((lane & 7) + (qa & 1) * 8) * WROW + ((qa >> 1) * 8) * 2;
    const int b_loff = (lane & 7) * WROW + qa * 16;

    const int ntiles = (T_ * S_) / 128;   // 2048
    for (int rt = blockIdx.x; rt < ntiles; rt += gridDim.x) {
        __syncthreads();
        const u32* src = (const u32*)(g_hh + (size_t)rt * 128 * H_);
        for (int i = tid; i < 128 * 64; i += 512) {
            int row = i >> 6, kp = i & 63;
            *(u32*)(sm + OFF_AH + row * WROW + kp * 4) = src[i];
        }
        __syncthreads();

        u32 ahi[8][4];
        const u32 abase_h = sbase + OFF_AH + mt * 16 * WROW + a_loff;
#pragma unroll
        for (int ks = 0; ks < 8; ks++) LDSM4(ahi[ks], abase_h + ks * 32);

#pragma unroll 2
        for (int nt = half * 32; nt < half * 32 + 32; nt++) {
            const int n0 = nt * 8;
            u32 bb[8][2];
#pragma unroll
            for (int kc = 0; kc < 4; kc++) {
                u32 r[4];
                LDSM4(r, sbase + OFF_W + n0 * WROW + b_loff + kc * 64);
                bb[kc * 2][0] = r[0]; bb[kc * 2][1] = r[1];
                bb[kc * 2 + 1][0] = r[2]; bb[kc * 2 + 1][1] = r[3];
            }
            float2 bbv = *(const float2*)&br[n0 + tid4 * 2];
            float D[4] = {bbv.x, bbv.y, bbv.x, bbv.y};
#pragma unroll
            for (int ks = 0; ks < 8; ks++) mma_f16(D, ahi[ks], bb[ks][0], bb[ks][1]);

            size_t rowA = ((size_t)rt * 128 + mt * 16 + grp) * G4H;
            size_t rowB = rowA + 8 * G4H;
            *(u32*)&g_xph[rowA + n0 + tid4 * 2] = packh(D[0], D[1]);
            *(u32*)&g_xph[rowB + n0 + tid4 * 2] = packh(D[2], D[3]);
        }
    }
}

// ---------------- GCN -------------------------------------------------------------
// k_lin1: xl1 = feats @ W1^T; also writes h1-init = bias + selfloop term.
__global__ void k_lin1(const float* __restrict__ w, const float* __restrict__ bias) {
    __shared__ float fr[8][H_];
    int r0 = blockIdx.x * 8, tid = threadIdx.x;   // 512 blocks, 128 thr
    for (int i = tid; i < 8 * H_; i += 128) {
        int r = i >> 7, k = i & 127;
        fr[r][k] = __half2float(g_hh[((size_t)(T_ - 1) * S_ + r0 + r) * H_ + k]);
    }
    __syncthreads();
    const float* wr = w + tid * H_;
    float acc[8] = {0, 0, 0, 0, 0, 0, 0, 0};
#pragma unroll 4
    for (int k = 0; k < H_; k++) {
        float wk = wr[k];
#pragma unroll
        for (int r = 0; r < 8; r++) acc[r] = fmaf(fr[r][k], wk, acc[r]);
    }
    float bv = bias[tid];
#pragma unroll
    for (int r = 0; r < 8; r++) {
        g_xl1[(r0 + r) * G1_ + tid] = acc[r];
        float d = g_dis[(r0 + r) & (N_ - 1)];
        g_h1[(r0 + r) * G1_ + tid] = bv + acc[r] * d * d;
    }
}

__global__ void k_lin2(const float* __restrict__ w, const float* __restrict__ bias) {
    __shared__ float fr[8][G1_];
    int r0 = blockIdx.x * 8, tid = threadIdx.x;   // 512 blocks, 64 thr
    for (int i = tid; i < 8 * G1_; i += 64) {
        int r = i >> 7, k = i & 127;
        fr[r][k] = fmaxf(g_h1[(r0 + r) * G1_ + k], 0.0f);
    }
    __syncthreads();
    const float* wr = w + tid * G1_;
    float acc[8] = {0, 0, 0, 0, 0, 0, 0, 0};
#pragma unroll 4
    for (int k = 0; k < G1_; k++) {
        float wk = wr[k];
#pragma unroll
        for (int r = 0; r < 8; r++) acc[r] = fmaf(fr[r][k], wk, acc[r]);
    }
    float bv = bias[tid];
#pragma unroll
    for (int r = 0; r < 8; r++) {
        g_xl2[(r0 + r) * G2_ + tid] = acc[r];
        float d = g_dis[(r0 + r) & (N_ - 1)];
        g_h2[(r0 + r) * G2_ + tid] = bv + acc[r] * d * d;
    }
}

template <int Gd>
__global__ void k_agg_edge(const void* __restrict__ ei) {
    constexpr int G4 = Gd / 4;
    const float* xl = (Gd == G1_) ? g_xl1 : g_xl2;
    float* outb     = (Gd == G1_) ? g_h1  : g_h2;
    int i = blockIdx.x * blockDim.x + threadIdx.x;
    constexpr int per = B_ * G4;
    if (i >= E_ * per) return;
    int e = i / per;
    int r = i - e * per;
    int b = r / G4;
    int g4 = r - b * G4;
    int is64 = g_is64;
    int src = edge_at(ei, is64, e);
    int dst = edge_at(ei, is64, E_ + e);
    float norm = g_dis[src] * g_dis[dst];
    float4 v = *(const float4*)&xl[(b * N_ + src) * Gd + g4 * 4];
    float* o = &outb[(b * N_ + dst) * Gd + g4 * 4];
    atomicAdd(o + 0, v.x * norm);
    atomicAdd(o + 1, v.y * norm);
    atomicAdd(o + 2, v.z * norm);
    atomicAdd(o + 3, v.w * norm);
}

__global__ void k_final(const float* __restrict__ cls_w,
                        const float* __restrict__ cls_b,
                        float* __restrict__ out) {
    int b = blockIdx.x, tid = threadIdx.x;
    __shared__ float red[256];
    float a = 0.0f;
    for (int i = tid; i < N_ * G2_; i += 256) {
        int g = i & (G2_ - 1);
        a = fmaf(fmaxf(g_h2[b * (N_ * G2_) + i], 0.0f), cls_w[g], a);
    }
    red[tid] = a;
    __syncthreads();
    for (int s = 128; s > 0; s >>= 1) {
        if (tid < s) red[tid] += red[tid + s];
        __syncthreads();
    }
    if (tid == 0) out[b] = red[0] * (1.0f / N_) + cls_b[0];
}

// ---------------- launch -----------------------------------------------------------
extern "C" void kernel_launch(void* const* d_in, const int* in_sizes, int n_in,
                              void* d_out, int out_size) {
    const float* x      = (const float*)d_in[0];
    const void*  ei     = d_in[1];
    const float* w_ih0  = (const float*)d_in[2];
    const float* w_hh0  = (const float*)d_in[3];
    const float* b_ih0  = (const float*)d_in[4];
    const float* b_hh0  = (const float*)d_in[5];
    const float* w_ih1  = (const float*)d_in[6];
    const float* w_hh1  = (const float*)d_in[7];
    const float* b_ih1  = (const float*)d_in[8];
    const float* b_hh1  = (const float*)d_in[9];
    const float* w_ih2  = (const float*)d_in[10];
    const float* w_hh2  = (const float*)d_in[11];
    const float* b_ih2  = (const float*)d_in[12];
    const float* b_hh2  = (const float*)d_in[13];
    const float* gcn1_w = (const float*)d_in[14];
    const float* gcn1_b = (const float*)d_in[15];
    const float* gcn2_w = (const float*)d_in[16];
    const float* gcn2_b = (const float*)d_in[17];
    const float* cls_w  = (const float*)d_in[18];
    const float* cls_b  = (const float*)d_in[19];
    float* out = (float*)d_out;

    u32 *whh, *wih;
    float *br, *w0r;
    cudaGetSymbolAddress((void**)&whh, g_whh_h);
    cudaGetSymbolAddress((void**)&wih, g_wih_h);
    cudaGetSymbolAddress((void**)&br, g_br);
    cudaGetSymbolAddress((void**)&w0r, g_w0r);

    cudaFuncSetAttribute(rec_mma<0, 1>, cudaFuncAttributeMaxDynamicSharedMemorySize, REC_SM);
    cudaFuncSetAttribute(rec_mma<1, 1>, cudaFuncAttributeMaxDynamicSharedMemorySize, REC_SM);
    cudaFuncSetAttribute(rec_mma<1, 0>, cudaFuncAttributeMaxDynamicSharedMemorySize, REC_SM);
    cudaFuncSetAttribute(proj_mma, cudaFuncAttributeMaxDynamicSharedMemorySize, PROJ_SM);

    constexpr int WN = G4H * 64;
    const int RB = S_ / 32;   // 128 blocks

    // layer 0
    k_edge_prep<<<1, 512>>>(ei);
    k_prep_w<<<WN / 256, 256>>>(w_hh0, whh + 0 * WN);
    k_prep_bw0<<<2, 256>>>(b_ih0, b_hh0, w_ih0);
    rec_mma<0, 1><<<RB, 512, REC_SM>>>(x, whh + 0 * WN, w0r, br + 0 * G4H);

    // layer 1
    k_prep_w<<<WN / 256, 256>>>(w_ih1, wih + 0 * WN);
    k_prep_b<<<2, 256>>>(b_ih1, b_hh1, br + 1 * G4H);
    proj_mma<<<148, 512, PROJ_SM>>>(wih + 0 * WN, br + 1 * G4H);
    k_prep_w<<<WN / 256, 256>>>(w_hh1, whh + 1 * WN);
    rec_mma<1, 1><<<RB, 512, REC_SM>>>(nullptr, whh + 1 * WN, nullptr, nullptr);

    // layer 2
    k_prep_w<<<WN / 256, 256>>>(w_ih2, wih + 1 * WN);
    k_prep_b<<<2, 256>>>(b_ih2, b_hh2, br + 2 * G4H);
    proj_mma<<<148, 512, PROJ_SM>>>(wih + 1 * WN, br + 2 * G4H);
    k_prep_w<<<WN / 256, 256>>>(w_hh2, whh + 2 * WN);
    rec_mma<1, 0><<<RB, 512, REC_SM>>>(nullptr, whh + 2 * WN, nullptr, nullptr);

    // GCN
    k_lin1<<<S_ / 8, 128>>>(gcn1_w, gcn1_b);
    k_agg_edge<G1_><<<(E_ * B_ * (G1_ / 4) + 255) / 256, 256>>>(ei);
    k_lin2<<<S_ / 8, 64>>>(gcn2_w, gcn2_b);
    k_agg_edge<G2_><<<(E_ * B_ * (G2_ / 4) + 255) / 256, 256>>>(ei);
    k_final<<<B_, 256>>>(cls_w, cls_b, out);
}

// round 11
// speedup vs baseline: 6.9637x; 1.1631x over previous
#include <cuda_runtime.h>
#include <cuda_fp16.h>

#define DINLINE __device__ __forceinline__
typedef unsigned int u32;
typedef unsigned short u16;

constexpr int B_ = 8, T_ = 64, N_ = 512, H_ = 128, E_ = 8192;
constexpr int S_ = B_ * N_;       // 4096 sequences
constexpr int G1_ = 128, G2_ = 64;
constexpr int G4H = 4 * H_;       // 512 gate rows

// ---------------- SMEM layout (byte offsets) -----------------------------------
constexpr int WROW    = 272;                   // 136 fp16 per row (128 + 8 pad)
constexpr int OFF_W   = 0;                     // 512*272 = 139264
constexpr int OFF_H   = 139264;                // h planes (2 x 32 x 272), fp16
constexpr int HPLANE  = 32 * WROW;             // 8704
constexpr int OFF_SX  = OFF_H + 2 * HPLANE;    // 156672 (MODE 0 only)
constexpr int OFF_W0S = OFF_SX + 8192;
constexpr int OFF_BRS = OFF_W0S + 2048;
constexpr int REC_SM  = OFF_BRS + 2048;        // 168960

constexpr int OFF_AH  = 139264;                // proj: A plane 128*272
constexpr int APLANE  = 128 * WROW;            // 34816
constexpr int PROJ_SM = OFF_AH + APLANE;       // 174080

// ---------------- device scratch (static globals; no allocation) ---------------
__device__ __half g_hh [(size_t)T_ * S_ * H_];   // [t*S+s][j]    64 MiB
__device__ __half g_xph[(size_t)T_ * S_ * G4H];  // [t*S+s][4j+g] 256 MiB
__device__ u32   g_whh_h[3][G4H * 64];           // permuted fp16-pair W_hh
__device__ u32   g_wih_h[2][G4H * 64];           // permuted fp16-pair W_ih
__device__ float g_br[3][G4H];                   // b_ih+b_hh permuted (4j+g)
__device__ float g_w0r[G4H];                     // w_ih0 permuted
__device__ float g_xl1[S_ * G1_];
__device__ float g_h1[S_ * G1_];
__device__ float g_xl2[S_ * G2_];
__device__ float g_h2[S_ * G2_];
__device__ float g_dis[N_];
__device__ int   g_is64;

// ---------------- helpers -------------------------------------------------------
DINLINE float tanhfast(float x) {
    float y;
    asm("tanh.approx.f32 %0, %1;" : "=f"(y) : "f"(x));
    return y;
}

DINLINE u32 smem_u32(const void* p) {
    u32 a;
    asm("{ .reg .u64 t; cvta.to.shared.u64 t, %1; cvt.u32.u64 %0, t; }" : "=r"(a) : "l"(p));
    return a;
}

DINLINE void mma_f16(float* D, const u32* A, u32 b0, u32 b1) {
    asm("mma.sync.aligned.m16n8k16.row.col.f32.f16.f16.f32 "
        "{%0,%1,%2,%3},{%4,%5,%6,%7},{%8,%9},{%0,%1,%2,%3};"
        : "+f"(D[0]), "+f"(D[1]), "+f"(D[2]), "+f"(D[3])
        : "r"(A[0]), "r"(A[1]), "r"(A[2]), "r"(A[3]), "r"(b0), "r"(b1));
}

#define LDSM4(R, ADDR) \
    asm volatile("ldmatrix.sync.aligned.m8n8.x4.shared.b16 {%0,%1,%2,%3},[%4];" \
        : "=r"((R)[0]), "=r"((R)[1]), "=r"((R)[2]), "=r"((R)[3]) : "r"(ADDR))

DINLINE u32 packh(float a, float b) {
    __half2 h = __floats2half2_rn(a, b);
    return *(u32*)&h;
}

DINLINE int edge_at(const void* p, int is64, int idx) {
    return is64 ? (int)((const long long*)p)[idx] : ((const int*)p)[idx];
}

// ---------------- fused edge prep: dtype detect + degree + rsqrt ----------------
__global__ void k_edge_prep(const void* __restrict__ ei) {
    __shared__ float sdeg[N_];
    __shared__ int nz;
    const int tid = threadIdx.x;   // 512 threads
    if (tid == 0) nz = 0;
    sdeg[tid] = 1.0f;              // self-loop
    __syncthreads();
    const int* ei32 = (const int*)ei;
    int acc = 0;
    for (int i = 1 + 2 * tid; i < 2 * E_; i += 1024) acc |= ei32[i];
    if (acc) atomicOr(&nz, 1);
    __syncthreads();
    int is64 = (nz == 0) ? 1 : 0;
    if (tid == 0) g_is64 = is64;
    for (int e = tid; e < E_; e += 512)
        atomicAdd(&sdeg[edge_at(ei, is64, E_ + e)], 1.0f);
    __syncthreads();
    g_dis[tid] = rsqrtf(sdeg[tid]);
}

// ---------------- weight prep: permute rows (4j+g), fp16-pair pack --------------
__global__ void k_prep_w(const float* __restrict__ w, u32* __restrict__ outw) {
    int i = blockIdx.x * blockDim.x + threadIdx.x;   // 512*64
    int colp = i >> 6, kp = i & 63;
    int j = colp >> 2, g = colp & 3;
    const float* wr = w + (g * H_ + j) * H_ + 2 * kp;
    outw[i] = packh(wr[0], wr[1]);
}

__global__ void k_prep_b(const float* __restrict__ bi, const float* __restrict__ bh,
                         float* __restrict__ outb) {
    int colp = blockIdx.x * blockDim.x + threadIdx.x;
    if (colp < G4H) {
        int j = colp >> 2, g = colp & 3;
        outb[colp] = bi[g * H_ + j] + bh[g * H_ + j];
    }
}

__global__ void k_prep_bw0(const float* __restrict__ bi, const float* __restrict__ bh,
                           const float* __restrict__ w) {
    int colp = blockIdx.x * blockDim.x + threadIdx.x;
    if (colp < G4H) {
        int j = colp >> 2, g = colp & 3;
        g_br[0][colp] = bi[g * H_ + j] + bh[g * H_ + j];
        g_w0r[colp]   = w[g * H_ + j];
    }
}

// ---------------- gate fold: shuffle, input add, activations, h write ------------
template <int MODE>
DINLINE void gate_fold(float* D, float& c_ref, char* sm, bool evn,
                       int myrow, int j, int t, int hw_off, uint2 xq) {
    float sv0 = evn ? D[2] : D[0];
    float rr0 = __shfl_xor_sync(0xffffffffu, sv0, 1);
    float sv1 = evn ? D[3] : D[1];
    float rr1 = __shfl_xor_sync(0xffffffffu, sv1, 1);
    float pi = evn ? D[0] : rr0;
    float pf = evn ? D[1] : rr1;
    float pg = evn ? rr0 : D[2];
    float po = evn ? rr1 : D[3];

    if (MODE == 1) {
        float2 fa = __half22float2(*(__half2*)&xq.x);
        float2 fb = __half22float2(*(__half2*)&xq.y);
        pi += fa.x; pf += fa.y; pg += fb.x; po += fb.y;
    } else {
        float xv = ((const float*)(sm + OFF_SX))[t * 32 + myrow];
        float4 w4 = ((const float4*)(sm + OFF_W0S))[j];
        float4 b4 = ((const float4*)(sm + OFF_BRS))[j];
        pi += xv * w4.x + b4.x;
        pf += xv * w4.y + b4.y;
        pg += xv * w4.z + b4.z;
        po += xv * w4.w + b4.w;
    }

    float si = fmaf(tanhfast(0.5f * pi), 0.5f, 0.5f);
    float sf = fmaf(tanhfast(0.5f * pf), 0.5f, 0.5f);
    float so = fmaf(tanhfast(0.5f * po), 0.5f, 0.5f);
    float cn = sf * c_ref + si * tanhfast(pg);
    c_ref = cn;
    float hv = so * tanhfast(cn);

    *(__half*)(sm + hw_off + myrow * WROW + j * 2) = __float2half_rn(hv);
}

// ---------------- tensor-core LSTM recurrence ------------------------------------
// 512 threads, 16 warps. Warp w owns gate-cols [32w, 32w+32) for BOTH m-tiles;
// its B (weight) fragments live in 64 registers, loaded ONCE before the t-loop.
// Per step: 16 A-LDSM4 total per warp (8 per m-tile), zero B-LDSM.
template <int MODE, int WRITE_ALL>
__global__ void __launch_bounds__(512, 1) rec_mma(
    const float* __restrict__ x,               // MODE 0
    const u32* __restrict__ w_h,               // [512][64] fp16 pairs
    const float* __restrict__ w0r,             // MODE 0
    const float* __restrict__ br0)             // MODE 0
{
    extern __shared__ __align__(16) char sm[];
    const u32 sbase = smem_u32(sm);

    const int tid = threadIdx.x, wid = tid >> 5, lane = tid & 31;
    const int grp = lane >> 2, tid4 = lane & 3;
    const bool evn = (tid4 & 1) == 0;
    const int cw = wid;                        // 32-col group
    const int s0 = blockIdx.x * 32;

    for (int i = tid; i < 512 * 64; i += 512) {
        int r = i >> 6, c = i & 63;
        *(u32*)(sm + OFF_W + r * WROW + c * 4) = w_h[i];
    }
    for (int i = tid; i < HPLANE / 4; i += 512)       // zero plane 0
        ((u32*)(sm + OFF_H))[i] = 0;
    if (MODE == 0) {
        float* sx = (float*)(sm + OFF_SX);
        for (int i = tid; i < 64 * 32; i += 512) {
            int t = i >> 5, m = i & 31;
            int s = s0 + m;
            sx[i] = x[(s >> 9) * (T_ * N_) + t * N_ + (s & (N_ - 1))];
        }
        if (tid < 512) {
            ((float*)(sm + OFF_W0S))[tid] = w0r[tid];
            ((float*)(sm + OFF_BRS))[tid] = br0[tid];
        }
    }
    __syncthreads();

    const int qa = lane >> 3;
    const int a_loff = ((lane & 7) + (qa & 1) * 8) * WROW + ((qa >> 1) * 8) * 2;
    const int b_loff = (lane & 7) * WROW + qa * 16;
    const int rowoff = evn ? grp : grp + 8;

    // resident B fragments: 4 n-tiles x 8 ks x 2 regs = 64 regs
    u32 breg[4][8][2];
#pragma unroll
    for (int nt = 0; nt < 4; nt++) {
        const int n0 = cw * 32 + nt * 8;
#pragma unroll
        for (int kc = 0; kc < 4; kc++) {
            u32 r[4];
            LDSM4(r, sbase + OFF_W + n0 * WROW + b_loff + kc * 64);
            breg[nt][kc * 2][0] = r[0]; breg[nt][kc * 2][1] = r[1];
            breg[nt][kc * 2 + 1][0] = r[2]; breg[nt][kc * 2 + 1][1] = r[3];
        }
    }

    float c_st[8];
#pragma unroll
    for (int q = 0; q < 8; q++) c_st[q] = 0.0f;

    for (int t = 0; t < T_; t++) {
        const int rb = t & 1, wb = rb ^ 1;
        const int hw_off = OFF_H + wb * HPLANE;

#pragma unroll
        for (int mt = 0; mt < 2; mt++) {
            const int myrow = mt * 16 + rowoff;

            // prefetch xp for this m-tile (self-consumed)
            uint2 xq[4];
            if (MODE == 1) {
                const __half* xpb = g_xph + ((size_t)t * S_ + s0 + myrow) * G4H
                                    + cw * 32 + (tid4 >> 1) * 4;
#pragma unroll
                for (int nt = 0; nt < 4; nt++)
                    xq[nt] = *(const uint2*)(xpb + nt * 8);
            }

            float D[4][4];
#pragma unroll
            for (int nt = 0; nt < 4; nt++)
#pragma unroll
                for (int q = 0; q < 4; q++) D[nt][q] = 0.0f;

            const u32 a_base = sbase + OFF_H + rb * HPLANE + mt * 16 * WROW + a_loff;
#pragma unroll
            for (int kchunk = 0; kchunk < 2; kchunk++) {
                u32 ahi[4][4];
#pragma unroll
                for (int k4 = 0; k4 < 4; k4++)
                    LDSM4(ahi[k4], a_base + (kchunk * 4 + k4) * 32);
#pragma unroll
                for (int nt = 0; nt < 4; nt++)
#pragma unroll
                    for (int k4 = 0; k4 < 4; k4++)
                        mma_f16(D[nt], ahi[k4],
                                breg[nt][kchunk * 4 + k4][0],
                                breg[nt][kchunk * 4 + k4][1]);
            }

#pragma unroll
            for (int nt = 0; nt < 4; nt++)
                gate_fold<MODE>(D[nt], c_st[mt * 4 + nt], sm, evn, myrow,
                                cw * 8 + nt * 2 + (tid4 >> 1), t, hw_off, xq[nt]);
        }

        __syncthreads();   // h(wb) complete; A-reads of rb done

        if (WRITE_ALL || t == T_ - 1) {
            for (int i = tid; i < 32 * 64; i += 512) {
                int r = i >> 6, jp = i & 63;
                u32 v = *(const u32*)(sm + hw_off + r * WROW + jp * 4);
                *(u32*)&g_hh[((size_t)t * S_ + s0 + r) * H_ + jp * 2] = v;
            }
        }
    }
}

// ---------------- tensor-core input projection (persistent, 512 thr) -------------
// Warp w owns cols [32w, 32w+32) with resident B fragments; loops over 8 m-tiles.
__global__ void __launch_bounds__(512, 1) proj_mma(
    const u32* __restrict__ w_h,
    const float* __restrict__ br)
{
    extern __shared__ __align__(16) char sm[];
    const u32 sbase = smem_u32(sm);

    const int tid = threadIdx.x, wid = tid >> 5, lane = tid & 31;
    const int grp = lane >> 2, tid4 = lane & 3;
    const int cw = wid;

    for (int i = tid; i < 512 * 64; i += 512) {
        int r = i >> 6, c = i & 63;
        *(u32*)(sm + OFF_W + r * WROW + c * 4) = w_h[i];
    }
    __syncthreads();

    const int qa = lane >> 3;
    const int a_loff = ((lane & 7) + (qa & 1) * 8) * WROW + ((qa >> 1) * 8) * 2;
    const int b_loff = (lane & 7) * WROW + qa * 16;

    // resident B fragments + bias
    u32 breg[4][8][2];
    float2 bbv[4];
#pragma unroll
    for (int nt = 0; nt < 4; nt++) {
        const int n0 = cw * 32 + nt * 8;
#pragma unroll
        for (int kc = 0; kc < 4; kc++) {
            u32 r[4];
            LDSM4(r, sbase + OFF_W + n0 * WROW + b_loff + kc * 64);
            breg[nt][kc * 2][0] = r[0]; breg[nt][kc * 2][1] = r[1];
            breg[nt][kc * 2 + 1][0] = r[2]; breg[nt][kc * 2 + 1][1] = r[3];
        }
        bbv[nt] = *(const float2*)&br[n0 + tid4 * 2];
    }

    const int ntiles = (T_ * S_) / 128;   // 2048
    for (int rt = blockIdx.x; rt < ntiles; rt += gridDim.x) {
        __syncthreads();
        const u32* src = (const u32*)(g_hh + (size_t)rt * 128 * H_);
        for (int i = tid; i < 128 * 64; i += 512) {
            int row = i >> 6, kp = i & 63;
            *(u32*)(sm + OFF_AH + row * WROW + kp * 4) = src[i];
        }
        __syncthreads();

#pragma unroll 1
        for (int mt = 0; mt < 8; mt++) {
            u32 ahi[8][4];
            const u32 abase = sbase + OFF_AH + mt * 16 * WROW + a_loff;
#pragma unroll
            for (int ks = 0; ks < 8; ks++) LDSM4(ahi[ks], abase + ks * 32);

#pragma unroll
            for (int nt = 0; nt < 4; nt++) {
                const int n0 = cw * 32 + nt * 8;
                float D[4] = {bbv[nt].x, bbv[nt].y, bbv[nt].x, bbv[nt].y};
#pragma unroll
                for (int ks = 0; ks < 8; ks++)
                    mma_f16(D, ahi[ks], breg[nt][ks][0], breg[nt][ks][1]);

                size_t rowA = ((size_t)rt * 128 + mt * 16 + grp) * G4H;
                size_t rowB = rowA + 8 * G4H;
                *(u32*)&g_xph[rowA + n0 + tid4 * 2] = packh(D[0], D[1]);
                *(u32*)&g_xph[rowB + n0 + tid4 * 2] = packh(D[2], D[3]);
            }
        }
    }
}

// ---------------- GCN -------------------------------------------------------------
__global__ void k_lin1(const float* __restrict__ w, const float* __restrict__ bias) {
    __shared__ float fr[8][H_];
    int r0 = blockIdx.x * 8, tid = threadIdx.x;   // 512 blocks, 128 thr
    for (int i = tid; i < 8 * H_; i += 128) {
        int r = i >> 7, k = i & 127;
        fr[r][k] = __half2float(g_hh[((size_t)(T_ - 1) * S_ + r0 + r) * H_ + k]);
    }
    __syncthreads();
    const float* wr = w + tid * H_;
    float acc[8] = {0, 0, 0, 0, 0, 0, 0, 0};
#pragma unroll 4
    for (int k = 0; k < H_; k++) {
        float wk = wr[k];
#pragma unroll
        for (int r = 0; r < 8; r++) acc[r] = fmaf(fr[r][k], wk, acc[r]);
    }
    float bv = bias[tid];
#pragma unroll
    for (int r = 0; r < 8; r++) {
        g_xl1[(r0 + r) * G1_ + tid] = acc[r];
        float d = g_dis[(r0 + r) & (N_ - 1)];
        g_h1[(r0 + r) * G1_ + tid] = bv + acc[r] * d * d;
    }
}

__global__ void k_lin2(const float* __restrict__ w, const float* __restrict__ bias) {
    __shared__ float fr[8][G1_];
    int r0 = blockIdx.x * 8, tid = threadIdx.x;   // 512 blocks, 64 thr
    for (int i = tid; i < 8 * G1_; i += 64) {
        int r = i >> 7, k = i & 127;
        fr[r][k] = fmaxf(g_h1[(r0 + r) * G1_ + k], 0.0f);
    }
    __syncthreads();
    const float* wr = w + tid * G1_;
    float acc[8] = {0, 0, 0, 0, 0, 0, 0, 0};
#pragma unroll 4
    for (int k = 0; k < G1_; k++) {
        float wk = wr[k];
#pragma unroll
        for (int r = 0; r < 8; r++) acc[r] = fmaf(fr[r][k], wk, acc[r]);
    }
    float bv = bias[tid];
#pragma unroll
    for (int r = 0; r < 8; r++) {
        g_xl2[(r0 + r) * G2_ + tid] = acc[r];
        float d = g_dis[(r0 + r) & (N_ - 1)];
        g_h2[(r0 + r) * G2_ + tid] = bv + acc[r] * d * d;
    }
}

template <int Gd>
__global__ void k_agg_edge(const void* __restrict__ ei) {
    constexpr int G4 = Gd / 4;
    const float* xl = (Gd == G1_) ? g_xl1 : g_xl2;
    float* outb     = (Gd == G1_) ? g_h1  : g_h2;
    int i = blockIdx.x * blockDim.x + threadIdx.x;
    constexpr int per = B_ * G4;
    if (i >= E_ * per) return;
    int e = i / per;
    int r = i - e * per;
    int b = r / G4;
    int g4 = r - b * G4;
    int is64 = g_is64;
    int src = edge_at(ei, is64, e);
    int dst = edge_at(ei, is64, E_ + e);
    float norm = g_dis[src] * g_dis[dst];
    float4 v = *(const float4*)&xl[(b * N_ + src) * Gd + g4 * 4];
    float* o = &outb[(b * N_ + dst) * Gd + g4 * 4];
    atomicAdd(o + 0, v.x * norm);
    atomicAdd(o + 1, v.y * norm);
    atomicAdd(o + 2, v.z * norm);
    atomicAdd(o + 3, v.w * norm);
}

__global__ void k_final(const float* __restrict__ cls_w,
                        const float* __restrict__ cls_b,
                        float* __restrict__ out) {
    int b = blockIdx.x, tid = threadIdx.x;
    __shared__ float red[256];
    float a = 0.0f;
    for (int i = tid; i < N_ * G2_; i += 256) {
        int g = i & (G2_ - 1);
        a = fmaf(fmaxf(g_h2[b * (N_ * G2_) + i], 0.0f), cls_w[g], a);
    }
    red[tid] = a;
    __syncthreads();
    for (int s = 128; s > 0; s >>= 1) {
        if (tid < s) red[tid] += red[tid + s];
        __syncthreads();
    }
    if (tid == 0) out[b] = red[0] * (1.0f / N_) + cls_b[0];
}

// ---------------- launch -----------------------------------------------------------
extern "C" void kernel_launch(void* const* d_in, const int* in_sizes, int n_in,
                              void* d_out, int out_size) {
    const float* x      = (const float*)d_in[0];
    const void*  ei     = d_in[1];
    const float* w_ih0  = (const float*)d_in[2];
    const float* w_hh0  = (const float*)d_in[3];
    const float* b_ih0  = (const float*)d_in[4];
    const float* b_hh0  = (const float*)d_in[5];
    const float* w_ih1  = (const float*)d_in[6];
    const float* w_hh1  = (const float*)d_in[7];
    const float* b_ih1  = (const float*)d_in[8];
    const float* b_hh1  = (const float*)d_in[9];
    const float* w_ih2  = (const float*)d_in[10];
    const float* w_hh2  = (const float*)d_in[11];
    const float* b_ih2  = (const float*)d_in[12];
    const float* b_hh2  = (const float*)d_in[13];
    const float* gcn1_w = (const float*)d_in[14];
    const float* gcn1_b = (const float*)d_in[15];
    const float* gcn2_w = (const float*)d_in[16];
    const float* gcn2_b = (const float*)d_in[17];
    const float* cls_w  = (const float*)d_in[18];
    const float* cls_b  = (const float*)d_in[19];
    float* out = (float*)d_out;

    u32 *whh, *wih;
    float *br, *w0r;
    cudaGetSymbolAddress((void**)&whh, g_whh_h);
    cudaGetSymbolAddress((void**)&wih, g_wih_h);
    cudaGetSymbolAddress((void**)&br, g_br);
    cudaGetSymbolAddress((void**)&w0r, g_w0r);

    cudaFuncSetAttribute(rec_mma<0, 1>, cudaFuncAttributeMaxDynamicSharedMemorySize, REC_SM);
    cudaFuncSetAttribute(rec_mma<1, 1>, cudaFuncAttributeMaxDynamicSharedMemorySize, REC_SM);
    cudaFuncSetAttribute(rec_mma<1, 0>, cudaFuncAttributeMaxDynamicSharedMemorySize, REC_SM);
    cudaFuncSetAttribute(proj_mma, cudaFuncAttributeMaxDynamicSharedMemorySize, PROJ_SM);

    constexpr int WN = G4H * 64;
    const int RB = S_ / 32;   // 128 blocks

    // layer 0
    k_edge_prep<<<1, 512>>>(ei);
    k_prep_w<<<WN / 256, 256>>>(w_hh0, whh + 0 * WN);
    k_prep_bw0<<<2, 256>>>(b_ih0, b_hh0, w_ih0);
    rec_mma<0, 1><<<RB, 512, REC_SM>>>(x, whh + 0 * WN, w0r, br + 0 * G4H);

    // layer 1
    k_prep_w<<<WN / 256, 256>>>(w_ih1, wih + 0 * WN);
    k_prep_b<<<2, 256>>>(b_ih1, b_hh1, br + 1 * G4H);
    proj_mma<<<148, 512, PROJ_SM>>>(wih + 0 * WN, br + 1 * G4H);
    k_prep_w<<<WN / 256, 256>>>(w_hh1, whh + 1 * WN);
    rec_mma<1, 1><<<RB, 512, REC_SM>>>(nullptr, whh + 1 * WN, nullptr, nullptr);

    // layer 2
    k_prep_w<<<WN / 256, 256>>>(w_ih2, wih + 1 * WN);
    k_prep_b<<<2, 256>>>(b_ih2, b_hh2, br + 2 * G4H);
    proj_mma<<<148, 512, PROJ_SM>>>(wih + 1 * WN, br + 2 * G4H);
    k_prep_w<<<WN / 256, 256>>>(w_hh2, whh + 2 * WN);
    rec_mma<1, 0><<<RB, 512, REC_SM>>>(nullptr, whh + 2 * WN, nullptr, nullptr);

    // GCN
    k_lin1<<<S_ / 8, 128>>>(gcn1_w, gcn1_b);
    k_agg_edge<G1_><<<(E_ * B_ * (G1_ / 4) + 255) / 256, 256>>>(ei);
    k_lin2<<<S_ / 8, 64>>>(gcn2_w, gcn2_b);
    k_agg_edge<G2_><<<(E_ * B_ * (G2_ / 4) + 255) / 256, 256>>>(ei);
    k_final<<<B_, 256>>>(cls_w, cls_b, out);
}